// round 1
// baseline (speedup 1.0000x reference)
#include <cuda_runtime.h>
#include <math.h>

#define MAXN 50000
#define MAXE 400000

// Scratch (static device globals — no allocation allowed)
__device__ float g_tmp1[MAXN * 64];    // layer1 pre-activation accumulator
__device__ float g_h1[MAXN * 64];      // relu(layer1)
__device__ float g_tmp2[MAXN * 128];   // layer2 accumulator

// ---------------------------------------------------------------------------
// Kernel 1: tmp1[n] = b1 + feat[n] @ loop_w1, feat[n] = emb[h_ids[n]]
// 8 nodes per block, 256 threads. W1 (64x64 = 16KB) staged in smem.
// ---------------------------------------------------------------------------
__global__ void k_loop1(const float* __restrict__ emb,
                        const int* __restrict__ h_ids,
                        const float* __restrict__ W,
                        const float* __restrict__ b1,
                        int n) {
    __shared__ float Ws[64 * 64];
    __shared__ float fs[8 * 64];
    for (int i = threadIdx.x; i < 4096; i += 256) Ws[i] = W[i];
    int base = blockIdx.x * 8;
    for (int i = threadIdx.x; i < 512; i += 256) {
        int node = base + (i >> 6);
        int col = i & 63;
        fs[i] = (node < n) ? emb[(size_t)h_ids[node] * 64 + col] : 0.f;
    }
    __syncthreads();
#pragma unroll
    for (int r = 0; r < 2; r++) {
        int j = threadIdx.x + r * 256;
        int ln = j >> 6, col = j & 63;
        int node = base + ln;
        if (node < n) {
            float acc = b1[col];
            const float* f = &fs[ln * 64];
#pragma unroll
            for (int k = 0; k < 64; k++) acc += f[k] * Ws[k * 64 + col];
            g_tmp1[(size_t)node * 64 + col] = acc;
        }
    }
}

// ---------------------------------------------------------------------------
// Kernel 2: layer-1 edge messages, atomicAdd into tmp1.
// 4 edges per block, 64 threads/edge. Per-edge weight row (512 f) in smem.
// msg[o] = sum_i x[b*8+i] * w[b*64 + i*8 + oo],  b=o>>3, oo=o&7
// ---------------------------------------------------------------------------
__global__ void k_edge1(const float* __restrict__ emb,
                        const int* __restrict__ h_ids,
                        const int* __restrict__ src,
                        const int* __restrict__ dst,
                        const int* __restrict__ rel,
                        const float* __restrict__ norm,
                        const float* __restrict__ w1,
                        int ne) {
    __shared__ float xs[4][64];
    __shared__ __align__(16) float ws[4][512];
    int g = threadIdx.x >> 6;
    int t = threadIdx.x & 63;
    int e = blockIdx.x * 4 + g;
    bool valid = (e < ne);
    int d = 0;
    float nm = 0.f;
    if (valid) {
        int s = src[e];
        d = dst[e];
        int r = rel[e];
        nm = norm[e];
        xs[g][t] = emb[(size_t)h_ids[s] * 64 + t];
        const float4* wr = (const float4*)(w1 + (size_t)r * 512);
        float4* wd = (float4*)ws[g];
        wd[t] = wr[t];
        wd[t + 64] = wr[t + 64];
    }
    __syncthreads();
    if (valid) {
        int b = t >> 3, oo = t & 7;
        const float* xb = &xs[g][b * 8];
        const float* wb = &ws[g][b * 64 + oo];
        float acc = 0.f;
#pragma unroll
        for (int i = 0; i < 8; i++) acc += xb[i] * wb[i * 8];
        atomicAdd(&g_tmp1[(size_t)d * 64 + t], acc * nm);
    }
}

// ---------------------------------------------------------------------------
// Kernel 3: h1 = relu(tmp1); tmp2 = b2 + h1 @ loop_w2 (64x128).
// 8 nodes/block, 256 threads. W2 (32KB) staged in smem.
// ---------------------------------------------------------------------------
__global__ void k_loop2(const float* __restrict__ W2,
                        const float* __restrict__ b2,
                        int n) {
    __shared__ float Ws[64 * 128];
    __shared__ float hs[8 * 64];
    for (int i = threadIdx.x; i < 8192; i += 256) Ws[i] = W2[i];
    int base = blockIdx.x * 8;
    for (int i = threadIdx.x; i < 512; i += 256) {
        int node = base + (i >> 6);
        int col = i & 63;
        float v = 0.f;
        if (node < n) {
            v = g_tmp1[(size_t)node * 64 + col];
            v = v > 0.f ? v : 0.f;
            g_h1[(size_t)node * 64 + col] = v;
        }
        hs[i] = v;
    }
    __syncthreads();
#pragma unroll
    for (int r = 0; r < 4; r++) {
        int j = threadIdx.x + r * 256;
        int ln = j >> 7, col = j & 127;
        int node = base + ln;
        if (node < n) {
            float acc = b2[col];
            const float* h = &hs[ln * 64];
#pragma unroll
            for (int k = 0; k < 64; k++) acc += h[k] * Ws[k * 128 + col];
            g_tmp2[(size_t)node * 128 + col] = acc;
        }
    }
}

// ---------------------------------------------------------------------------
// Kernel 4: layer-2 edge messages, atomicAdd into tmp2.
// 2 edges/block, 128 threads/edge. Per-edge weight row (1024 f) in smem.
// msg[o] = sum_i h1[b*8+i] * w[b*128 + i*16 + oo],  b=o>>4, oo=o&15
// ---------------------------------------------------------------------------
__global__ void k_edge2(const int* __restrict__ src,
                        const int* __restrict__ dst,
                        const int* __restrict__ rel,
                        const float* __restrict__ norm,
                        const float* __restrict__ w2,
                        int ne) {
    __shared__ float xs[2][64];
    __shared__ __align__(16) float ws[2][1024];
    int g = threadIdx.x >> 7;
    int t = threadIdx.x & 127;
    int e = blockIdx.x * 2 + g;
    bool valid = (e < ne);
    int d = 0;
    float nm = 0.f;
    if (valid) {
        int s = src[e];
        d = dst[e];
        int r = rel[e];
        nm = norm[e];
        if (t < 64) xs[g][t] = g_h1[(size_t)s * 64 + t];
        const float4* wr = (const float4*)(w2 + (size_t)r * 1024);
        float4* wd = (float4*)ws[g];
        wd[t] = wr[t];
        wd[t + 128] = wr[t + 128];
    }
    __syncthreads();
    if (valid) {
        int b = t >> 4, oo = t & 15;
        const float* xb = &xs[g][b * 8];
        const float* wb = &ws[g][b * 128 + oo];
        float acc = 0.f;
#pragma unroll
        for (int i = 0; i < 8; i++) acc += xb[i] * wb[i * 16];
        atomicAdd(&g_tmp2[(size_t)d * 128 + t], acc * nm);
    }
}

// ---------------------------------------------------------------------------
// Kernel 5: reparameterize: out = m + sqrt(softplus(raw_v)+1e-8) * eps
// ---------------------------------------------------------------------------
__global__ void k_final(const float* __restrict__ eps,
                        float* __restrict__ out,
                        int n) {
    int idx = blockIdx.x * blockDim.x + threadIdx.x;
    if (idx < n * 64) {
        int node = idx >> 6, col = idx & 63;
        float m = g_tmp2[(size_t)node * 128 + col];
        float rv = g_tmp2[(size_t)node * 128 + 64 + col];
        // softplus, overflow-safe
        float sp = (rv > 20.f) ? rv : log1pf(expf(rv));
        out[idx] = m + sqrtf(sp + 1e-8f) * eps[idx];
    }
}

// ---------------------------------------------------------------------------
extern "C" void kernel_launch(void* const* d_in, const int* in_sizes, int n_in,
                              void* d_out, int out_size) {
    const float* emb   = (const float*)d_in[0];
    const float* norm  = (const float*)d_in[1];
    const float* eps   = (const float*)d_in[2];
    const float* w1    = (const float*)d_in[3];
    const float* lw1   = (const float*)d_in[4];
    const float* b1    = (const float*)d_in[5];
    const float* w2    = (const float*)d_in[6];
    const float* lw2   = (const float*)d_in[7];
    const float* b2    = (const float*)d_in[8];
    const int*   h_ids = (const int*)d_in[9];
    const int*   src   = (const int*)d_in[10];
    const int*   dst   = (const int*)d_in[11];
    const int*   rel   = (const int*)d_in[12];

    int n  = in_sizes[9];   // num nodes (h_ids)
    int ne = in_sizes[10];  // num edges (src)

    k_loop1<<<(n + 7) / 8, 256>>>(emb, h_ids, lw1, b1, n);
    k_edge1<<<(ne + 3) / 4, 256>>>(emb, h_ids, src, dst, rel, norm, w1, ne);
    k_loop2<<<(n + 7) / 8, 256>>>(lw2, b2, n);
    k_edge2<<<(ne + 1) / 2, 256>>>(src, dst, rel, norm, w2, ne);
    k_final<<<(n * 64 + 255) / 256, 256>>>(eps, (float*)d_out, n);
}

// round 2
// speedup vs baseline: 1.1891x; 1.1891x over previous
#include <cuda_runtime.h>
#include <math.h>

#define MAXN 50000
#define MAXE 400000
#define NREL 200
#define CHUNK 64

// Scratch (static device globals — no allocation allowed)
__device__ __align__(16) float g_tmp1[MAXN * 64];    // layer1 accumulator
__device__ __align__(16) float g_h1[MAXN * 64];      // relu(layer1)
__device__ __align__(16) float g_tmp2[MAXN * 128];   // layer2 accumulator

// sort scratch
__device__ int g_hist[NREL];
__device__ int g_cursor[NREL];
__device__ int g_offs[NREL + 1];   // edge offset per relation (exclusive scan)
__device__ int g_bpre[NREL + 1];   // block offset per relation
__device__ int g_perm[MAXE];       // edge ids sorted by relation

// ---------------------------------------------------------------------------
// Sort kernels
// ---------------------------------------------------------------------------
__global__ void k_zero() {
    int i = blockIdx.x * blockDim.x + threadIdx.x;
    if (i < NREL) { g_hist[i] = 0; g_cursor[i] = 0; }
}

__global__ void k_hist(const int* __restrict__ rel, int ne) {
    __shared__ int sh[NREL];
    for (int i = threadIdx.x; i < NREL; i += blockDim.x) sh[i] = 0;
    __syncthreads();
    int stride = gridDim.x * blockDim.x;
    for (int e = blockIdx.x * blockDim.x + threadIdx.x; e < ne; e += stride)
        atomicAdd(&sh[rel[e]], 1);
    __syncthreads();
    for (int i = threadIdx.x; i < NREL; i += blockDim.x)
        if (sh[i]) atomicAdd(&g_hist[i], sh[i]);
}

__global__ void k_scan() {
    if (threadIdx.x == 0) {
        int s = 0, bp = 0;
        for (int r = 0; r < NREL; r++) {
            g_offs[r] = s;
            g_bpre[r] = bp;
            s += g_hist[r];
            bp += (g_hist[r] + CHUNK - 1) / CHUNK;
        }
        g_offs[NREL] = s;
        g_bpre[NREL] = bp;
    }
}

__global__ void k_scatter(const int* __restrict__ rel, int ne) {
    int stride = gridDim.x * blockDim.x;
    for (int e = blockIdx.x * blockDim.x + threadIdx.x; e < ne; e += stride) {
        int r = rel[e];
        int pos = g_offs[r] + atomicAdd(&g_cursor[r], 1);
        g_perm[pos] = e;
    }
}

// ---------------------------------------------------------------------------
// Kernel: tmp1[n] = b1 + feat[n] @ loop_w1 (64x64). 32 nodes/block.
// ---------------------------------------------------------------------------
__global__ void k_loop1(const float* __restrict__ emb,
                        const int* __restrict__ h_ids,
                        const float* __restrict__ W,
                        const float* __restrict__ b1,
                        int n) {
    __shared__ float Ws[64 * 64];
    __shared__ float fs[32 * 64];
    for (int i = threadIdx.x; i < 4096; i += 256) Ws[i] = W[i];
    int base = blockIdx.x * 32;
    for (int i = threadIdx.x; i < 2048; i += 256) {
        int node = base + (i >> 6);
        int col = i & 63;
        fs[i] = (node < n) ? emb[(size_t)h_ids[node] * 64 + col] : 0.f;
    }
    __syncthreads();
#pragma unroll
    for (int r = 0; r < 8; r++) {
        int j = threadIdx.x + r * 256;
        int ln = j >> 6, col = j & 63;
        int node = base + ln;
        if (node < n) {
            float acc = b1[col];
            const float* f = &fs[ln * 64];
#pragma unroll
            for (int k = 0; k < 64; k++) acc += f[k] * Ws[k * 64 + col];
            g_tmp1[(size_t)node * 64 + col] = acc;
        }
    }
}

// ---------------------------------------------------------------------------
// Layer-1 edge kernel (relation-sorted).
// One block = one 64-edge chunk of one relation. Weight (512f) loaded once.
// 16 groups of 16 threads; each group handles one edge per iteration;
// each thread computes 4 outputs, red.v4 scatter.
// ---------------------------------------------------------------------------
__global__ void k_edge1s(const float* __restrict__ emb,
                         const int* __restrict__ h_ids,
                         const int* __restrict__ src,
                         const int* __restrict__ dst,
                         const float* __restrict__ norm,
                         const float* __restrict__ w1) {
    int bid = blockIdx.x;
    if (bid >= g_bpre[NREL]) return;
    // binary search: largest r with bpre[r] <= bid
    int lo = 0, hi = NREL;
    while (lo < hi - 1) {
        int mid = (lo + hi) >> 1;
        if (g_bpre[mid] <= bid) lo = mid; else hi = mid;
    }
    int r = lo;
    int ebase = g_offs[r] + (bid - g_bpre[r]) * CHUNK;
    int cnt = min(CHUNK, g_offs[r + 1] - ebase);

    __shared__ float ws[512];
    __shared__ float xs[16][64];
    int tid = threadIdx.x;
    ws[tid] = w1[(size_t)r * 512 + tid];
    ws[tid + 256] = w1[(size_t)r * 512 + 256 + tid];
    __syncthreads();

    int g = tid >> 4, t = tid & 15;
#pragma unroll
    for (int it = 0; it < 4; it++) {
        int j = it * 16 + g;
        int d = 0; float nm = 0.f; bool v = (j < cnt);
        if (v) {
            int e = g_perm[ebase + j];
            d = dst[e];
            nm = norm[e];
            int s = h_ids[src[e]];
            ((float4*)xs[g])[t] = ((const float4*)(emb + (size_t)s * 64))[t];
        }
        __syncwarp();
        if (v) {
            int b = t >> 1;
            const float* xb = &xs[g][b * 8];
            const float* wb = &ws[b * 64 + (t & 1) * 4];
            float a0 = 0.f, a1 = 0.f, a2 = 0.f, a3 = 0.f;
#pragma unroll
            for (int i = 0; i < 8; i++) {
                float x = xb[i];
                const float* w = &wb[i * 8];
                a0 += x * w[0]; a1 += x * w[1]; a2 += x * w[2]; a3 += x * w[3];
            }
            a0 *= nm; a1 *= nm; a2 *= nm; a3 *= nm;
            float* addr = &g_tmp1[(size_t)d * 64 + t * 4];
            asm volatile("red.global.add.v4.f32 [%0], {%1,%2,%3,%4};"
                         :: "l"(addr), "f"(a0), "f"(a1), "f"(a2), "f"(a3)
                         : "memory");
        }
        __syncwarp();
    }
}

// ---------------------------------------------------------------------------
// Kernel: h1 = relu(tmp1); tmp2 = b2 + h1 @ loop_w2 (64x128). 32 nodes/block.
// ---------------------------------------------------------------------------
__global__ void k_loop2(const float* __restrict__ W2,
                        const float* __restrict__ b2,
                        int n) {
    __shared__ float Ws[64 * 128];
    __shared__ float hs[32 * 64];
    for (int i = threadIdx.x; i < 8192; i += 256) Ws[i] = W2[i];
    int base = blockIdx.x * 32;
    for (int i = threadIdx.x; i < 2048; i += 256) {
        int node = base + (i >> 6);
        int col = i & 63;
        float v = 0.f;
        if (node < n) {
            v = g_tmp1[(size_t)node * 64 + col];
            v = v > 0.f ? v : 0.f;
            g_h1[(size_t)node * 64 + col] = v;
        }
        hs[i] = v;
    }
    __syncthreads();
#pragma unroll
    for (int r = 0; r < 16; r++) {
        int j = threadIdx.x + r * 256;
        int ln = j >> 7, col = j & 127;
        int node = base + ln;
        if (node < n) {
            float acc = b2[col];
            const float* h = &hs[ln * 64];
#pragma unroll
            for (int k = 0; k < 64; k++) acc += h[k] * Ws[k * 128 + col];
            g_tmp2[(size_t)node * 128 + col] = acc;
        }
    }
}

// ---------------------------------------------------------------------------
// Layer-2 edge kernel (relation-sorted). Weight (1024f) loaded once per block.
// 8 warps; each warp handles one edge per iteration; each thread 4 outputs.
// ---------------------------------------------------------------------------
__global__ void k_edge2s(const int* __restrict__ src,
                         const int* __restrict__ dst,
                         const float* __restrict__ norm,
                         const float* __restrict__ w2) {
    int bid = blockIdx.x;
    if (bid >= g_bpre[NREL]) return;
    int lo = 0, hi = NREL;
    while (lo < hi - 1) {
        int mid = (lo + hi) >> 1;
        if (g_bpre[mid] <= bid) lo = mid; else hi = mid;
    }
    int r = lo;
    int ebase = g_offs[r] + (bid - g_bpre[r]) * CHUNK;
    int cnt = min(CHUNK, g_offs[r + 1] - ebase);

    __shared__ __align__(16) float ws[1024];
    __shared__ float xs[8][64];
    int tid = threadIdx.x;
    ((float4*)ws)[tid] = ((const float4*)(w2 + (size_t)r * 1024))[tid];
    __syncthreads();

    int g = tid >> 5, t = tid & 31;
#pragma unroll
    for (int it = 0; it < 8; it++) {
        int j = it * 8 + g;
        int d = 0; float nm = 0.f; bool v = (j < cnt);
        if (v) {
            int e = g_perm[ebase + j];
            d = dst[e];
            nm = norm[e];
            int s = src[e];
            ((float2*)xs[g])[t] = ((const float2*)(g_h1 + (size_t)s * 64))[t];
        }
        __syncwarp();
        if (v) {
            int b = t >> 2;
            const float* xb = &xs[g][b * 8];
            const float* wb = &ws[b * 128 + (t & 3) * 4];
            float a0 = 0.f, a1 = 0.f, a2 = 0.f, a3 = 0.f;
#pragma unroll
            for (int i = 0; i < 8; i++) {
                float x = xb[i];
                const float* w = &wb[i * 16];
                a0 += x * w[0]; a1 += x * w[1]; a2 += x * w[2]; a3 += x * w[3];
            }
            a0 *= nm; a1 *= nm; a2 *= nm; a3 *= nm;
            float* addr = &g_tmp2[(size_t)d * 128 + t * 4];
            asm volatile("red.global.add.v4.f32 [%0], {%1,%2,%3,%4};"
                         :: "l"(addr), "f"(a0), "f"(a1), "f"(a2), "f"(a3)
                         : "memory");
        }
        __syncwarp();
    }
}

// ---------------------------------------------------------------------------
// Final: out = m + sqrt(softplus(raw_v)+1e-8) * eps
// ---------------------------------------------------------------------------
__global__ void k_final(const float* __restrict__ eps,
                        float* __restrict__ out,
                        int n) {
    int idx = blockIdx.x * blockDim.x + threadIdx.x;
    if (idx < n * 64) {
        int node = idx >> 6, col = idx & 63;
        float m = g_tmp2[(size_t)node * 128 + col];
        float rv = g_tmp2[(size_t)node * 128 + 64 + col];
        float sp = (rv > 20.f) ? rv : log1pf(expf(rv));
        out[idx] = m + sqrtf(sp + 1e-8f) * eps[idx];
    }
}

// ---------------------------------------------------------------------------
extern "C" void kernel_launch(void* const* d_in, const int* in_sizes, int n_in,
                              void* d_out, int out_size) {
    const float* emb   = (const float*)d_in[0];
    const float* norm  = (const float*)d_in[1];
    const float* eps   = (const float*)d_in[2];
    const float* w1    = (const float*)d_in[3];
    const float* lw1   = (const float*)d_in[4];
    const float* b1    = (const float*)d_in[5];
    const float* w2    = (const float*)d_in[6];
    const float* lw2   = (const float*)d_in[7];
    const float* b2    = (const float*)d_in[8];
    const int*   h_ids = (const int*)d_in[9];
    const int*   src   = (const int*)d_in[10];
    const int*   dst   = (const int*)d_in[11];
    const int*   rel   = (const int*)d_in[12];

    int n  = in_sizes[9];
    int ne = in_sizes[10];

    int maxb = ne / CHUNK + NREL + 1;  // upper bound on relation-chunk blocks

    k_zero<<<1, 256>>>();
    k_hist<<<96, 256>>>(rel, ne);
    k_scan<<<1, 32>>>();
    k_scatter<<<96, 256>>>(rel, ne);

    k_loop1<<<(n + 31) / 32, 256>>>(emb, h_ids, lw1, b1, n);
    k_edge1s<<<maxb, 256>>>(emb, h_ids, src, dst, norm, w1);
    k_loop2<<<(n + 31) / 32, 256>>>(lw2, b2, n);
    k_edge2s<<<maxb, 256>>>(src, dst, norm, w2);
    k_final<<<(n * 64 + 255) / 256, 256>>>(eps, (float*)d_out, n);
}

// round 3
// speedup vs baseline: 1.3824x; 1.1625x over previous
#include <cuda_runtime.h>
#include <math.h>

#define MAXN 50000
#define MAXE 400000
#define NREL 200
#define CHUNK 64
#define SCHUNK 4096   // edges per scatter block (256 thr * 16)

// Scratch (static device globals — no allocation allowed)
__device__ __align__(16) float g_tmp1[MAXN * 64];    // layer1 accumulator
__device__ __align__(16) float g_h1[MAXN * 64];      // relu(layer1)
__device__ __align__(16) float g_tmp2[MAXN * 128];   // layer2 accumulator

// sort scratch
__device__ int g_hist[NREL];
__device__ int g_cursor[NREL];
__device__ int g_offs[NREL + 1];   // edge offset per relation (exclusive scan)
__device__ int g_bpre[NREL + 1];   // block offset per relation
__device__ int   g_src_s[MAXE];    // h_ids[src], sorted by relation
__device__ int   g_dst_s[MAXE];    // dst, sorted by relation
__device__ float g_norm_s[MAXE];   // norm, sorted by relation

// ---------------------------------------------------------------------------
__global__ void k_zero() {
    int i = blockIdx.x * blockDim.x + threadIdx.x;
    if (i < NREL) { g_hist[i] = 0; g_cursor[i] = 0; }
}

__global__ void k_hist(const int* __restrict__ rel, int ne) {
    __shared__ int sh[NREL];
    for (int i = threadIdx.x; i < NREL; i += blockDim.x) sh[i] = 0;
    __syncthreads();
    int stride = gridDim.x * blockDim.x;
    for (int e = blockIdx.x * blockDim.x + threadIdx.x; e < ne; e += stride)
        atomicAdd(&sh[rel[e]], 1);
    __syncthreads();
    for (int i = threadIdx.x; i < NREL; i += blockDim.x)
        if (sh[i]) atomicAdd(&g_hist[i], sh[i]);
}

__global__ void k_scan() {
    if (threadIdx.x == 0) {
        int s = 0, bp = 0;
        for (int r = 0; r < NREL; r++) {
            g_offs[r] = s;
            g_bpre[r] = bp;
            s += g_hist[r];
            bp += (g_hist[r] + CHUNK - 1) / CHUNK;
        }
        g_offs[NREL] = s;
        g_bpre[NREL] = bp;
    }
}

// Two-level scatter: shared-mem local ranks + one global atomic per (block,rel).
// Also materializes sorted src (with h_ids folded), dst, norm.
__global__ void k_scatter(const int* __restrict__ rel,
                          const int* __restrict__ src,
                          const int* __restrict__ dst,
                          const float* __restrict__ norm,
                          const int* __restrict__ h_ids,
                          int ne) {
    __shared__ int cur[NREL];
    __shared__ int base[NREL];
    for (int i = threadIdx.x; i < NREL; i += 256) cur[i] = 0;
    __syncthreads();
    int start = blockIdx.x * SCHUNK;
    int lr[16], lrank[16];
#pragma unroll
    for (int it = 0; it < 16; it++) {
        int e = start + it * 256 + threadIdx.x;
        if (e < ne) {
            int r = rel[e];
            lr[it] = r;
            lrank[it] = atomicAdd(&cur[r], 1);
        }
    }
    __syncthreads();
    for (int i = threadIdx.x; i < NREL; i += 256) {
        int c = cur[i];
        base[i] = c ? atomicAdd(&g_cursor[i], c) : 0;
    }
    __syncthreads();
#pragma unroll
    for (int it = 0; it < 16; it++) {
        int e = start + it * 256 + threadIdx.x;
        if (e < ne) {
            int r = lr[it];
            int pos = g_offs[r] + base[r] + lrank[it];
            g_src_s[pos] = h_ids[src[e]];
            g_dst_s[pos] = dst[e];
            g_norm_s[pos] = norm[e];
        }
    }
}

// ---------------------------------------------------------------------------
// tmp1[n] = b1 + feat[n] @ loop_w1 (64x64). 32 nodes/block.
// ---------------------------------------------------------------------------
__global__ void k_loop1(const float* __restrict__ emb,
                        const int* __restrict__ h_ids,
                        const float* __restrict__ W,
                        const float* __restrict__ b1,
                        int n) {
    __shared__ float Ws[64 * 64];
    __shared__ float fs[32 * 64];
    for (int i = threadIdx.x; i < 4096; i += 256) Ws[i] = W[i];
    int base = blockIdx.x * 32;
    for (int i = threadIdx.x; i < 2048; i += 256) {
        int node = base + (i >> 6);
        int col = i & 63;
        fs[i] = (node < n) ? emb[(size_t)h_ids[node] * 64 + col] : 0.f;
    }
    __syncthreads();
#pragma unroll
    for (int r = 0; r < 8; r++) {
        int j = threadIdx.x + r * 256;
        int ln = j >> 6, col = j & 63;
        int node = base + ln;
        if (node < n) {
            float acc = b1[col];
            const float* f = &fs[ln * 64];
#pragma unroll
            for (int k = 0; k < 64; k++) acc += f[k] * Ws[k * 64 + col];
            g_tmp1[(size_t)node * 64 + col] = acc;
        }
    }
}

// ---------------------------------------------------------------------------
// Layer-1 edge kernel (relation-sorted, coalesced edge arrays).
// One block = 64-edge chunk of one relation; weight (512f) loaded once.
// ---------------------------------------------------------------------------
__global__ void k_edge1s(const float* __restrict__ emb,
                         const float* __restrict__ w1) {
    int bid = blockIdx.x;
    if (bid >= g_bpre[NREL]) return;
    int lo = 0, hi = NREL;
    while (lo < hi - 1) {
        int mid = (lo + hi) >> 1;
        if (g_bpre[mid] <= bid) lo = mid; else hi = mid;
    }
    int r = lo;
    int ebase = g_offs[r] + (bid - g_bpre[r]) * CHUNK;
    int cnt = min(CHUNK, g_offs[r + 1] - ebase);

    __shared__ float ws[512];
    __shared__ float xs[16][64];
    int tid = threadIdx.x;
    ws[tid] = w1[(size_t)r * 512 + tid];
    ws[tid + 256] = w1[(size_t)r * 512 + 256 + tid];
    __syncthreads();

    int g = tid >> 4, t = tid & 15;
#pragma unroll
    for (int it = 0; it < 4; it++) {
        int j = it * 16 + g;
        int d = 0; float nm = 0.f; bool v = (j < cnt);
        if (v) {
            d = g_dst_s[ebase + j];
            nm = g_norm_s[ebase + j];
            int s = g_src_s[ebase + j];
            ((float4*)xs[g])[t] = ((const float4*)(emb + (size_t)s * 64))[t];
        }
        __syncwarp();
        if (v) {
            int b = t >> 1;
            const float* xb = &xs[g][b * 8];
            const float* wb = &ws[b * 64 + (t & 1) * 4];
            float a0 = 0.f, a1 = 0.f, a2 = 0.f, a3 = 0.f;
#pragma unroll
            for (int i = 0; i < 8; i++) {
                float x = xb[i];
                const float* w = &wb[i * 8];
                a0 += x * w[0]; a1 += x * w[1]; a2 += x * w[2]; a3 += x * w[3];
            }
            a0 *= nm; a1 *= nm; a2 *= nm; a3 *= nm;
            float* addr = &g_tmp1[(size_t)d * 64 + t * 4];
            asm volatile("red.global.add.v4.f32 [%0], {%1,%2,%3,%4};"
                         :: "l"(addr), "f"(a0), "f"(a1), "f"(a2), "f"(a3)
                         : "memory");
        }
        __syncwarp();
    }
}

// ---------------------------------------------------------------------------
// h1 = relu(tmp1); tmp2 = b2 + h1 @ loop_w2 (64x128). 32 nodes/block.
// ---------------------------------------------------------------------------
__global__ void k_loop2(const float* __restrict__ W2,
                        const float* __restrict__ b2,
                        int n) {
    __shared__ float Ws[64 * 128];
    __shared__ float hs[32 * 64];
    for (int i = threadIdx.x; i < 8192; i += 256) Ws[i] = W2[i];
    int base = blockIdx.x * 32;
    for (int i = threadIdx.x; i < 2048; i += 256) {
        int node = base + (i >> 6);
        int col = i & 63;
        float v = 0.f;
        if (node < n) {
            v = g_tmp1[(size_t)node * 64 + col];
            v = v > 0.f ? v : 0.f;
            g_h1[(size_t)node * 64 + col] = v;
        }
        hs[i] = v;
    }
    __syncthreads();
#pragma unroll
    for (int r = 0; r < 16; r++) {
        int j = threadIdx.x + r * 256;
        int ln = j >> 7, col = j & 127;
        int node = base + ln;
        if (node < n) {
            float acc = b2[col];
            const float* h = &hs[ln * 64];
#pragma unroll
            for (int k = 0; k < 64; k++) acc += h[k] * Ws[k * 128 + col];
            g_tmp2[(size_t)node * 128 + col] = acc;
        }
    }
}

// ---------------------------------------------------------------------------
// Layer-2 edge kernel (relation-sorted). Weight (1024f) loaded once per block.
// ---------------------------------------------------------------------------
__global__ void k_edge2s(const float* __restrict__ w2) {
    int bid = blockIdx.x;
    if (bid >= g_bpre[NREL]) return;
    int lo = 0, hi = NREL;
    while (lo < hi - 1) {
        int mid = (lo + hi) >> 1;
        if (g_bpre[mid] <= bid) lo = mid; else hi = mid;
    }
    int r = lo;
    int ebase = g_offs[r] + (bid - g_bpre[r]) * CHUNK;
    int cnt = min(CHUNK, g_offs[r + 1] - ebase);

    __shared__ __align__(16) float ws[1024];
    __shared__ float xs[8][64];
    int tid = threadIdx.x;
    ((float4*)ws)[tid] = ((const float4*)(w2 + (size_t)r * 1024))[tid];
    __syncthreads();

    int g = tid >> 5, t = tid & 31;
#pragma unroll
    for (int it = 0; it < 8; it++) {
        int j = it * 8 + g;
        int d = 0; float nm = 0.f; bool v = (j < cnt);
        if (v) {
            d = g_dst_s[ebase + j];
            nm = g_norm_s[ebase + j];
            int s = g_src_s[ebase + j];
            ((float2*)xs[g])[t] = ((const float2*)(g_h1 + (size_t)s * 64))[t];
        }
        __syncwarp();
        if (v) {
            int b = t >> 2;
            const float* xb = &xs[g][b * 8];
            const float* wb = &ws[b * 128 + (t & 3) * 4];
            float a0 = 0.f, a1 = 0.f, a2 = 0.f, a3 = 0.f;
#pragma unroll
            for (int i = 0; i < 8; i++) {
                float x = xb[i];
                const float* w = &wb[i * 16];
                a0 += x * w[0]; a1 += x * w[1]; a2 += x * w[2]; a3 += x * w[3];
            }
            a0 *= nm; a1 *= nm; a2 *= nm; a3 *= nm;
            float* addr = &g_tmp2[(size_t)d * 128 + t * 4];
            asm volatile("red.global.add.v4.f32 [%0], {%1,%2,%3,%4};"
                         :: "l"(addr), "f"(a0), "f"(a1), "f"(a2), "f"(a3)
                         : "memory");
        }
        __syncwarp();
    }
}

// ---------------------------------------------------------------------------
__global__ void k_final(const float* __restrict__ eps,
                        float* __restrict__ out,
                        int n) {
    int idx = blockIdx.x * blockDim.x + threadIdx.x;
    if (idx < n * 64) {
        int node = idx >> 6, col = idx & 63;
        float m = g_tmp2[(size_t)node * 128 + col];
        float rv = g_tmp2[(size_t)node * 128 + 64 + col];
        float sp = (rv > 20.f) ? rv : log1pf(expf(rv));
        out[idx] = m + sqrtf(sp + 1e-8f) * eps[idx];
    }
}

// ---------------------------------------------------------------------------
extern "C" void kernel_launch(void* const* d_in, const int* in_sizes, int n_in,
                              void* d_out, int out_size) {
    const float* emb   = (const float*)d_in[0];
    const float* norm  = (const float*)d_in[1];
    const float* eps   = (const float*)d_in[2];
    const float* w1    = (const float*)d_in[3];
    const float* lw1   = (const float*)d_in[4];
    const float* b1    = (const float*)d_in[5];
    const float* w2    = (const float*)d_in[6];
    const float* lw2   = (const float*)d_in[7];
    const float* b2    = (const float*)d_in[8];
    const int*   h_ids = (const int*)d_in[9];
    const int*   src   = (const int*)d_in[10];
    const int*   dst   = (const int*)d_in[11];
    const int*   rel   = (const int*)d_in[12];

    int n  = in_sizes[9];
    int ne = in_sizes[10];

    int maxb = ne / CHUNK + NREL + 1;
    int sblocks = (ne + SCHUNK - 1) / SCHUNK;

    k_zero<<<1, 256>>>();
    k_hist<<<96, 256>>>(rel, ne);
    k_scan<<<1, 32>>>();
    k_scatter<<<sblocks, 256>>>(rel, src, dst, norm, h_ids, ne);

    k_loop1<<<(n + 31) / 32, 256>>>(emb, h_ids, lw1, b1, n);
    k_edge1s<<<maxb, 256>>>(emb, w1);
    k_loop2<<<(n + 31) / 32, 256>>>(lw2, b2, n);
    k_edge2s<<<maxb, 256>>>(w2);
    k_final<<<(n * 64 + 255) / 256, 256>>>(eps, (float*)d_out, n);
}

// round 4
// speedup vs baseline: 2.3906x; 1.7292x over previous
#include <cuda_runtime.h>
#include <math.h>

#define MAXN 50000
#define MAXE 400000
#define NREL 200
#define CHUNK 256
#define MAXB 2048
#define SCHUNK 4096

typedef unsigned long long ull;

// Scratch (static device globals — no allocation allowed)
__device__ __align__(16) float g_tmp1[MAXN * 64];
__device__ __align__(16) float g_h1[MAXN * 64];
__device__ __align__(16) float g_tmp2[MAXN * 128];

// sort scratch
__device__ int g_hist[NREL];
__device__ int g_cursor[NREL];
__device__ int g_offs[NREL + 1];
__device__ int g_bpre[NREL + 1];
__device__ int g_blockrel[MAXB];       // (rel << 16) | chunk_idx
__device__ int   g_src_s[MAXE];
__device__ int   g_dst_s[MAXE];
__device__ float g_norm_s[MAXE];

// ---------------------------------------------------------------------------
// f32x2 packed-math helpers
// ---------------------------------------------------------------------------
__device__ __forceinline__ ull pack2(float x, float y) {
    ull r; asm("mov.b64 %0, {%1,%2};" : "=l"(r) : "f"(x), "f"(y)); return r;
}
__device__ __forceinline__ void unpack2(ull v, float& x, float& y) {
    asm("mov.b64 {%0,%1}, %2;" : "=f"(x), "=f"(y) : "l"(v));
}
__device__ __forceinline__ void fma2(ull& acc, ull a, ull b) {
    asm("fma.rn.f32x2 %0, %1, %2, %0;" : "+l"(acc) : "l"(a), "l"(b));
}
__device__ __forceinline__ void red4(float* addr, float a, float b, float c, float d) {
    asm volatile("red.global.add.v4.f32 [%0], {%1,%2,%3,%4};"
                 :: "l"(addr), "f"(a), "f"(b), "f"(c), "f"(d) : "memory");
}

// ---------------------------------------------------------------------------
// Sort pipeline
// ---------------------------------------------------------------------------
__global__ void k_zero() {
    int i = blockIdx.x * blockDim.x + threadIdx.x;
    if (i < NREL) { g_hist[i] = 0; g_cursor[i] = 0; }
}

__global__ void k_hist(const int* __restrict__ rel, int ne) {
    __shared__ int sh[NREL];
    for (int i = threadIdx.x; i < NREL; i += blockDim.x) sh[i] = 0;
    __syncthreads();
    int stride = gridDim.x * blockDim.x;
    for (int e = blockIdx.x * blockDim.x + threadIdx.x; e < ne; e += stride)
        atomicAdd(&sh[rel[e]], 1);
    __syncthreads();
    for (int i = threadIdx.x; i < NREL; i += blockDim.x)
        if (sh[i]) atomicAdd(&g_hist[i], sh[i]);
}

// Parallel inclusive scan of hist (edge offsets) and chunk counts (block offsets).
__global__ void k_scan() {
    __shared__ int sh[256], sb[256];
    int t = threadIdx.x;
    int h = (t < NREL) ? g_hist[t] : 0;
    int b = (h + CHUNK - 1) / CHUNK;
    sh[t] = h; sb[t] = b;
    __syncthreads();
    for (int off = 1; off < 256; off <<= 1) {
        int vh = 0, vb = 0;
        if (t >= off) { vh = sh[t - off]; vb = sb[t - off]; }
        __syncthreads();
        sh[t] += vh; sb[t] += vb;
        __syncthreads();
    }
    if (t < NREL) { g_offs[t + 1] = sh[t]; g_bpre[t + 1] = sb[t]; }
    if (t == 0) { g_offs[0] = 0; g_bpre[0] = 0; }
}

// block -> (relation, chunk index) lookup table
__global__ void k_blockmap() {
    for (int r = threadIdx.x; r < NREL; r += 256) {
        int b0 = g_bpre[r], b1 = g_bpre[r + 1];
        for (int b = b0; b < b1; b++)
            g_blockrel[b] = (r << 16) | (b - b0);
    }
}

// Two-level scatter: smem local ranks + one global atomic per (block, rel).
__global__ void k_scatter(const int* __restrict__ rel,
                          const int* __restrict__ src,
                          const int* __restrict__ dst,
                          const float* __restrict__ norm,
                          const int* __restrict__ h_ids,
                          int ne) {
    __shared__ int cur[NREL];
    __shared__ int base[NREL];
    for (int i = threadIdx.x; i < NREL; i += 256) cur[i] = 0;
    __syncthreads();
    int start = blockIdx.x * SCHUNK;
    int lr[16], lrank[16];
#pragma unroll
    for (int it = 0; it < 16; it++) {
        int e = start + it * 256 + threadIdx.x;
        if (e < ne) {
            int r = rel[e];
            lr[it] = r;
            lrank[it] = atomicAdd(&cur[r], 1);
        }
    }
    __syncthreads();
    for (int i = threadIdx.x; i < NREL; i += 256) {
        int c = cur[i];
        base[i] = c ? atomicAdd(&g_cursor[i], c) : 0;
    }
    __syncthreads();
#pragma unroll
    for (int it = 0; it < 16; it++) {
        int e = start + it * 256 + threadIdx.x;
        if (e < ne) {
            int r = lr[it];
            int pos = g_offs[r] + base[r] + lrank[it];
            g_src_s[pos] = h_ids[src[e]];
            g_dst_s[pos] = dst[e];
            g_norm_s[pos] = norm[e];
        }
    }
}

// ---------------------------------------------------------------------------
// tmp1[n] = b1 + feat[n] @ loop_w1 (64x64). 32 nodes/block.
// ---------------------------------------------------------------------------
__global__ void k_loop1(const float* __restrict__ emb,
                        const int* __restrict__ h_ids,
                        const float* __restrict__ W,
                        const float* __restrict__ b1,
                        int n) {
    __shared__ float Ws[64 * 64];
    __shared__ float fs[32 * 64];
    for (int i = threadIdx.x; i < 4096; i += 256) Ws[i] = W[i];
    int base = blockIdx.x * 32;
    for (int i = threadIdx.x; i < 2048; i += 256) {
        int node = base + (i >> 6);
        int col = i & 63;
        fs[i] = (node < n) ? emb[(size_t)h_ids[node] * 64 + col] : 0.f;
    }
    __syncthreads();
#pragma unroll
    for (int r = 0; r < 8; r++) {
        int j = threadIdx.x + r * 256;
        int ln = j >> 6, col = j & 63;
        int node = base + ln;
        if (node < n) {
            float acc = b1[col];
            const float* f = &fs[ln * 64];
#pragma unroll
            for (int k = 0; k < 64; k++) acc += f[k] * Ws[k * 64 + col];
            g_tmp1[(size_t)node * 64 + col] = acc;
        }
    }
}

// ---------------------------------------------------------------------------
// Layer-1 edges. CHUNK=256 per block, 16 groups x 16 threads, register weights,
// f32x2 FMA, norm folded into x, prefetched x.
// ---------------------------------------------------------------------------
__global__ void __launch_bounds__(256) k_edge1s(const float* __restrict__ emb,
                                                const float* __restrict__ w1) {
    if ((int)blockIdx.x >= g_bpre[NREL]) return;
    int info = g_blockrel[blockIdx.x];
    int r = info >> 16, ci = info & 0xFFFF;
    int ebase = g_offs[r] + ci * CHUNK;
    int cnt = min(CHUNK, g_offs[r + 1] - ebase);

    __shared__ int ssrc[CHUNK];
    __shared__ int sdst[CHUNK];
    __shared__ float snorm[CHUNK];
    __shared__ float xs[16][64];

    int tid = threadIdx.x;
    if (tid < cnt) {
        ssrc[tid] = g_src_s[ebase + tid];
        sdst[tid] = g_dst_s[ebase + tid];
        snorm[tid] = g_norm_s[ebase + tid];
    }
    int t2 = tid & 15, g = tid >> 4;
    int b = t2 >> 1, q = t2 & 1;
    // per-thread weights: w1[r*512 + b*64 + i*8 + q*4 .. +3], i=0..7
    const float4* wrow = (const float4*)(w1 + (size_t)r * 512 + b * 64 + q * 4);
    ull wlo[8], whi[8];
#pragma unroll
    for (int i = 0; i < 8; i++) {
        float4 w4 = wrow[i * 2];
        wlo[i] = pack2(w4.x, w4.y);
        whi[i] = pack2(w4.z, w4.w);
    }
    __syncthreads();

    int jc = g;
    bool vc = (jc < cnt);
    float4 xc = make_float4(0.f, 0.f, 0.f, 0.f);
    if (vc) xc = ((const float4*)(emb + (size_t)ssrc[jc] * 64))[t2];

    for (int it = 0; it < 16; it++) {
        if (vc) {
            float nm = snorm[jc];
            xc.x *= nm; xc.y *= nm; xc.z *= nm; xc.w *= nm;
            ((float4*)xs[g])[t2] = xc;
        }
        __syncwarp();
        int jn = jc + 16;
        bool vn = (jn < cnt);
        float4 xn = make_float4(0.f, 0.f, 0.f, 0.f);
        if (vn) xn = ((const float4*)(emb + (size_t)ssrc[jn] * 64))[t2];
        if (vc) {
            ull a0 = 0ULL, a1 = 0ULL;
            const float* xb = &xs[g][b * 8];
#pragma unroll
            for (int i = 0; i < 8; i++) {
                ull xx = pack2(xb[i], xb[i]);
                fma2(a0, xx, wlo[i]);
                fma2(a1, xx, whi[i]);
            }
            float f0, f1, f2, f3;
            unpack2(a0, f0, f1);
            unpack2(a1, f2, f3);
            red4(&g_tmp1[(size_t)sdst[jc] * 64 + b * 8 + q * 4], f0, f1, f2, f3);
        }
        __syncwarp();
        xc = xn; jc = jn; vc = vn;
    }
}

// ---------------------------------------------------------------------------
// h1 = relu(tmp1); tmp2 = b2 + h1 @ loop_w2 (64x128). 32 nodes/block.
// ---------------------------------------------------------------------------
__global__ void k_loop2(const float* __restrict__ W2,
                        const float* __restrict__ b2,
                        int n) {
    __shared__ float Ws[64 * 128];
    __shared__ float hs[32 * 64];
    for (int i = threadIdx.x; i < 8192; i += 256) Ws[i] = W2[i];
    int base = blockIdx.x * 32;
    for (int i = threadIdx.x; i < 2048; i += 256) {
        int node = base + (i >> 6);
        int col = i & 63;
        float v = 0.f;
        if (node < n) {
            v = g_tmp1[(size_t)node * 64 + col];
            v = v > 0.f ? v : 0.f;
            g_h1[(size_t)node * 64 + col] = v;
        }
        hs[i] = v;
    }
    __syncthreads();
#pragma unroll
    for (int r = 0; r < 16; r++) {
        int j = threadIdx.x + r * 256;
        int ln = j >> 7, col = j & 127;
        int node = base + ln;
        if (node < n) {
            float acc = b2[col];
            const float* h = &hs[ln * 64];
#pragma unroll
            for (int k = 0; k < 64; k++) acc += h[k] * Ws[k * 128 + col];
            g_tmp2[(size_t)node * 128 + col] = acc;
        }
    }
}

// ---------------------------------------------------------------------------
// Layer-2 edges. CHUNK=256 per block, warp per edge (8 warps), register
// weights, f32x2, norm folded into x, prefetched x.
// ---------------------------------------------------------------------------
__global__ void __launch_bounds__(256) k_edge2s(const float* __restrict__ w2) {
    if ((int)blockIdx.x >= g_bpre[NREL]) return;
    int info = g_blockrel[blockIdx.x];
    int r = info >> 16, ci = info & 0xFFFF;
    int ebase = g_offs[r] + ci * CHUNK;
    int cnt = min(CHUNK, g_offs[r + 1] - ebase);

    __shared__ int ssrc[CHUNK];
    __shared__ int sdst[CHUNK];
    __shared__ float snorm[CHUNK];
    __shared__ float xs[8][64];

    int tid = threadIdx.x;
    if (tid < cnt) {
        ssrc[tid] = g_src_s[ebase + tid];
        sdst[tid] = g_dst_s[ebase + tid];
        snorm[tid] = g_norm_s[ebase + tid];
    }
    int w = tid >> 5, t = tid & 31;
    int b = t >> 2, q = t & 3;
    // per-thread weights: w2[r*1024 + b*128 + i*16 + q*4 .. +3], i=0..7
    const float* wp = w2 + (size_t)r * 1024 + b * 128 + q * 4;
    ull wlo[8], whi[8];
#pragma unroll
    for (int i = 0; i < 8; i++) {
        float4 w4 = *(const float4*)(wp + i * 16);
        wlo[i] = pack2(w4.x, w4.y);
        whi[i] = pack2(w4.z, w4.w);
    }
    __syncthreads();

    int jc = w;
    bool vc = (jc < cnt);
    float2 xc = make_float2(0.f, 0.f);
    if (vc) xc = ((const float2*)(g_h1 + (size_t)ssrc[jc] * 64))[t];

    for (int it = 0; it < 32; it++) {
        if (vc) {
            float nm = snorm[jc];
            xc.x *= nm; xc.y *= nm;
            ((float2*)xs[w])[t] = xc;
        }
        __syncwarp();
        int jn = jc + 8;
        bool vn = (jn < cnt);
        float2 xn = make_float2(0.f, 0.f);
        if (vn) xn = ((const float2*)(g_h1 + (size_t)ssrc[jn] * 64))[t];
        if (vc) {
            ull a0 = 0ULL, a1 = 0ULL;
            const float* xb = &xs[w][b * 8];
#pragma unroll
            for (int i = 0; i < 8; i++) {
                ull xx = pack2(xb[i], xb[i]);
                fma2(a0, xx, wlo[i]);
                fma2(a1, xx, whi[i]);
            }
            float f0, f1, f2, f3;
            unpack2(a0, f0, f1);
            unpack2(a1, f2, f3);
            red4(&g_tmp2[(size_t)sdst[jc] * 128 + b * 16 + q * 4], f0, f1, f2, f3);
        }
        __syncwarp();
        xc = xn; jc = jn; vc = vn;
    }
}

// ---------------------------------------------------------------------------
// Final: out = m + sqrt(softplus(raw_v)+1e-8) * eps   (float4 vectorized)
// ---------------------------------------------------------------------------
__global__ void k_final(const float* __restrict__ eps,
                        float* __restrict__ out,
                        int n) {
    int gi = blockIdx.x * blockDim.x + threadIdx.x;   // float4 group index
    int total = n * 16;                               // n*64 floats / 4
    if (gi < total) {
        int node = gi >> 4, c4 = gi & 15;
        const float4* t2 = (const float4*)g_tmp2;
        float4 m = t2[(size_t)node * 32 + c4];
        float4 rv = t2[(size_t)node * 32 + 16 + c4];
        float4 e = ((const float4*)eps)[gi];
        float4 o;
        float sp;
        sp = (rv.x > 20.f) ? rv.x : log1pf(expf(rv.x)); o.x = m.x + sqrtf(sp + 1e-8f) * e.x;
        sp = (rv.y > 20.f) ? rv.y : log1pf(expf(rv.y)); o.y = m.y + sqrtf(sp + 1e-8f) * e.y;
        sp = (rv.z > 20.f) ? rv.z : log1pf(expf(rv.z)); o.z = m.z + sqrtf(sp + 1e-8f) * e.z;
        sp = (rv.w > 20.f) ? rv.w : log1pf(expf(rv.w)); o.w = m.w + sqrtf(sp + 1e-8f) * e.w;
        ((float4*)out)[gi] = o;
    }
}

// ---------------------------------------------------------------------------
extern "C" void kernel_launch(void* const* d_in, const int* in_sizes, int n_in,
                              void* d_out, int out_size) {
    const float* emb   = (const float*)d_in[0];
    const float* norm  = (const float*)d_in[1];
    const float* eps   = (const float*)d_in[2];
    const float* w1    = (const float*)d_in[3];
    const float* lw1   = (const float*)d_in[4];
    const float* b1    = (const float*)d_in[5];
    const float* w2    = (const float*)d_in[6];
    const float* lw2   = (const float*)d_in[7];
    const float* b2    = (const float*)d_in[8];
    const int*   h_ids = (const int*)d_in[9];
    const int*   src   = (const int*)d_in[10];
    const int*   dst   = (const int*)d_in[11];
    const int*   rel   = (const int*)d_in[12];

    int n  = in_sizes[9];
    int ne = in_sizes[10];

    int maxb = ne / CHUNK + NREL + 1;
    int sblocks = (ne + SCHUNK - 1) / SCHUNK;

    k_zero<<<1, 256>>>();
    k_hist<<<96, 256>>>(rel, ne);
    k_scan<<<1, 256>>>();
    k_blockmap<<<1, 256>>>();
    k_scatter<<<sblocks, 256>>>(rel, src, dst, norm, h_ids, ne);

    k_loop1<<<(n + 31) / 32, 256>>>(emb, h_ids, lw1, b1, n);
    k_edge1s<<<maxb, 256>>>(emb, w1);
    k_loop2<<<(n + 31) / 32, 256>>>(lw2, b2, n);
    k_edge2s<<<maxb, 256>>>(w2);
    k_final<<<(n * 16 + 255) / 256, 256>>>(eps, (float*)d_out, n);
}

// round 5
// speedup vs baseline: 2.4908x; 1.0419x over previous
#include <cuda_runtime.h>
#include <math.h>

#define MAXN 50000
#define MAXE 400000
#define NREL 200
#define CHUNK 256
#define MAXB 4096
#define SCHUNK 1024

typedef unsigned long long ull;

// Scratch (static device globals — no allocation allowed)
__device__ __align__(16) float g_tmp1[MAXN * 64];
__device__ __align__(16) float g_h1[MAXN * 64];
__device__ __align__(16) float g_tmp2[MAXN * 128];

// sort scratch
__device__ int g_hist[NREL];
__device__ int g_cursor[NREL];
__device__ int g_offs[NREL + 1];
__device__ int g_bpre[NREL + 1];
__device__ int g_blockrel[MAXB];
__device__ int   g_src_s[MAXE];
__device__ int   g_dst_s[MAXE];
__device__ float g_norm_s[MAXE];

// ---------------------------------------------------------------------------
// f32x2 packed-math helpers
// ---------------------------------------------------------------------------
__device__ __forceinline__ ull pack2(float x, float y) {
    ull r; asm("mov.b64 %0, {%1,%2};" : "=l"(r) : "f"(x), "f"(y)); return r;
}
__device__ __forceinline__ void unpack2(ull v, float& x, float& y) {
    asm("mov.b64 {%0,%1}, %2;" : "=f"(x), "=f"(y) : "l"(v));
}
__device__ __forceinline__ void fma2(ull& acc, ull a, ull b) {
    asm("fma.rn.f32x2 %0, %1, %2, %0;" : "+l"(acc) : "l"(a), "l"(b));
}
__device__ __forceinline__ void mul2(ull& a, ull b) {
    asm("mul.rn.f32x2 %0, %1, %2;" : "+l"(a) : "l"(a), "l"(b));
}
__device__ __forceinline__ void red4(float* addr, float a, float b, float c, float d) {
    asm volatile("red.global.add.v4.f32 [%0], {%1,%2,%3,%4};"
                 :: "l"(addr), "f"(a), "f"(b), "f"(c), "f"(d) : "memory");
}

// ---------------------------------------------------------------------------
// Sort pipeline
// ---------------------------------------------------------------------------
__global__ void k_zero() {
    int i = blockIdx.x * blockDim.x + threadIdx.x;
    if (i < NREL) { g_hist[i] = 0; g_cursor[i] = 0; }
}

__global__ void k_hist(const int* __restrict__ rel, int ne) {
    __shared__ int sh[NREL];
    for (int i = threadIdx.x; i < NREL; i += blockDim.x) sh[i] = 0;
    __syncthreads();
    int stride = gridDim.x * blockDim.x;
    for (int e = blockIdx.x * blockDim.x + threadIdx.x; e < ne; e += stride)
        atomicAdd(&sh[rel[e]], 1);
    __syncthreads();
    for (int i = threadIdx.x; i < NREL; i += blockDim.x)
        if (sh[i]) atomicAdd(&g_hist[i], sh[i]);
}

__global__ void k_scan() {
    __shared__ int sh[256], sb[256];
    int t = threadIdx.x;
    int h = (t < NREL) ? g_hist[t] : 0;
    int b = (h + CHUNK - 1) / CHUNK;
    sh[t] = h; sb[t] = b;
    __syncthreads();
    for (int off = 1; off < 256; off <<= 1) {
        int vh = 0, vb = 0;
        if (t >= off) { vh = sh[t - off]; vb = sb[t - off]; }
        __syncthreads();
        sh[t] += vh; sb[t] += vb;
        __syncthreads();
    }
    if (t < NREL) { g_offs[t + 1] = sh[t]; g_bpre[t + 1] = sb[t]; }
    if (t == 0) { g_offs[0] = 0; g_bpre[0] = 0; }
}

// block -> (relation, chunk index); parallel across relations
__global__ void k_blockmap() {
    int r = blockIdx.x;
    int b0 = g_bpre[r], b1 = g_bpre[r + 1];
    for (int b = b0 + threadIdx.x; b < b1; b += 32)
        g_blockrel[b] = (r << 16) | (b - b0);
}

// Two-level scatter: smem local ranks + one global atomic per (block, rel).
__global__ void k_scatter(const int* __restrict__ rel,
                          const int* __restrict__ src,
                          const int* __restrict__ dst,
                          const float* __restrict__ norm,
                          const int* __restrict__ h_ids,
                          int ne) {
    __shared__ int cur[NREL];
    __shared__ int base[NREL];
    for (int i = threadIdx.x; i < NREL; i += 256) cur[i] = 0;
    __syncthreads();
    int start = blockIdx.x * SCHUNK;
    int lr[4], lrank[4];
#pragma unroll
    for (int it = 0; it < 4; it++) {
        int e = start + it * 256 + threadIdx.x;
        if (e < ne) {
            int r = rel[e];
            lr[it] = r;
            lrank[it] = atomicAdd(&cur[r], 1);
        }
    }
    __syncthreads();
    for (int i = threadIdx.x; i < NREL; i += 256) {
        int c = cur[i];
        base[i] = c ? atomicAdd(&g_cursor[i], c) : 0;
    }
    __syncthreads();
#pragma unroll
    for (int it = 0; it < 4; it++) {
        int e = start + it * 256 + threadIdx.x;
        if (e < ne) {
            int r = lr[it];
            int pos = g_offs[r] + base[r] + lrank[it];
            g_src_s[pos] = h_ids[src[e]];
            g_dst_s[pos] = dst[e];
            g_norm_s[pos] = norm[e];
        }
    }
}

// ---------------------------------------------------------------------------
// tmp1[n] = b1 + feat[n] @ loop_w1 (64x64). 32 nodes/block.
// ---------------------------------------------------------------------------
__global__ void k_loop1(const float* __restrict__ emb,
                        const int* __restrict__ h_ids,
                        const float* __restrict__ W,
                        const float* __restrict__ b1,
                        int n) {
    __shared__ float Ws[64 * 64];
    __shared__ float fs[32 * 64];
    for (int i = threadIdx.x; i < 4096; i += 256) Ws[i] = W[i];
    int base = blockIdx.x * 32;
    for (int i = threadIdx.x; i < 2048; i += 256) {
        int node = base + (i >> 6);
        int col = i & 63;
        fs[i] = (node < n) ? emb[(size_t)h_ids[node] * 64 + col] : 0.f;
    }
    __syncthreads();
#pragma unroll
    for (int r = 0; r < 8; r++) {
        int j = threadIdx.x + r * 256;
        int ln = j >> 6, col = j & 63;
        int node = base + ln;
        if (node < n) {
            float acc = b1[col];
            const float* f = &fs[ln * 64];
#pragma unroll
            for (int k = 0; k < 64; k++) acc += f[k] * Ws[k * 64 + col];
            g_tmp1[(size_t)node * 64 + col] = acc;
        }
    }
}

// ---------------------------------------------------------------------------
// Layer-1 edges. 16 threads/edge (2 edges/warp), register weights (16 ull),
// per-thread direct x LDG with prefetch, no smem x, no syncs in loop.
// Thread (b=u>>1, q=u&1): outputs o = b*8 + q*4 .. +3.
// ---------------------------------------------------------------------------
__global__ void __launch_bounds__(256) k_edge1s(const float* __restrict__ emb,
                                                const float* __restrict__ w1) {
    if ((int)blockIdx.x >= g_bpre[NREL]) return;
    int info = g_blockrel[blockIdx.x];
    int r = info >> 16, ci = info & 0xFFFF;
    int ebase = g_offs[r] + ci * CHUNK;
    int cnt = min(CHUNK, g_offs[r + 1] - ebase);

    __shared__ int ssrc[CHUNK];
    __shared__ int sdst[CHUNK];
    __shared__ float snorm[CHUNK];

    int tid = threadIdx.x;
    int u = tid & 15;           // lane within edge
    int es = (tid >> 4) & 1;    // edge slot within warp
    int w = tid >> 5;           // warp id
    int b = u >> 1, q = u & 1;

    // per-thread weights: w1[r*512 + b*64 + i*8 + q*4 .. +3], i=0..7
    const float4* wrow = (const float4*)(w1 + (size_t)r * 512 + b * 64 + q * 4);
    ull wlo[8], whi[8];
#pragma unroll
    for (int i = 0; i < 8; i++) {
        float4 w4 = wrow[i * 2];
        wlo[i] = pack2(w4.x, w4.y);
        whi[i] = pack2(w4.z, w4.w);
    }

    if (tid < cnt) {
        ssrc[tid] = g_src_s[ebase + tid];
        sdst[tid] = g_dst_s[ebase + tid];
        snorm[tid] = g_norm_s[ebase + tid];
    }
    __syncthreads();

    int jc = w * 2 + es;                       // 16 edges per iteration
    bool vc = (jc < cnt);
    int jcc = vc ? jc : 0;
    const float4* xp = (const float4*)(emb + (size_t)ssrc[jcc] * 64 + b * 8);
    float4 xA = xp[0], xB = xp[1];

    for (int it = 0; it < 16; it++) {
        int jn = jc + 16;
        bool vn = (jn < cnt);
        int jnn = vn ? jn : 0;
        const float4* xq = (const float4*)(emb + (size_t)ssrc[jnn] * 64 + b * 8);
        float4 yA = xq[0], yB = xq[1];

        if (vc) {
            float nm = snorm[jc];
            ull a0 = 0ULL, a1 = 0ULL;
            ull xx;
            xx = pack2(xA.x, xA.x); fma2(a0, xx, wlo[0]); fma2(a1, xx, whi[0]);
            xx = pack2(xA.y, xA.y); fma2(a0, xx, wlo[1]); fma2(a1, xx, whi[1]);
            xx = pack2(xA.z, xA.z); fma2(a0, xx, wlo[2]); fma2(a1, xx, whi[2]);
            xx = pack2(xA.w, xA.w); fma2(a0, xx, wlo[3]); fma2(a1, xx, whi[3]);
            xx = pack2(xB.x, xB.x); fma2(a0, xx, wlo[4]); fma2(a1, xx, whi[4]);
            xx = pack2(xB.y, xB.y); fma2(a0, xx, wlo[5]); fma2(a1, xx, whi[5]);
            xx = pack2(xB.z, xB.z); fma2(a0, xx, wlo[6]); fma2(a1, xx, whi[6]);
            xx = pack2(xB.w, xB.w); fma2(a0, xx, wlo[7]); fma2(a1, xx, whi[7]);
            ull nn = pack2(nm, nm);
            mul2(a0, nn); mul2(a1, nn);
            float f0, f1, f2, f3;
            unpack2(a0, f0, f1);
            unpack2(a1, f2, f3);
            red4(&g_tmp1[(size_t)sdst[jc] * 64 + b * 8 + q * 4], f0, f1, f2, f3);
        }
        xA = yA; xB = yB; jc = jn; vc = vn;
    }
}

// ---------------------------------------------------------------------------
// h1 = relu(tmp1); tmp2 = b2 + h1 @ loop_w2 (64x128). 32 nodes/block.
// ---------------------------------------------------------------------------
__global__ void k_loop2(const float* __restrict__ W2,
                        const float* __restrict__ b2,
                        int n) {
    __shared__ float Ws[64 * 128];
    __shared__ float hs[32 * 64];
    for (int i = threadIdx.x; i < 8192; i += 256) Ws[i] = W2[i];
    int base = blockIdx.x * 32;
    for (int i = threadIdx.x; i < 2048; i += 256) {
        int node = base + (i >> 6);
        int col = i & 63;
        float v = 0.f;
        if (node < n) {
            v = g_tmp1[(size_t)node * 64 + col];
            v = v > 0.f ? v : 0.f;
            g_h1[(size_t)node * 64 + col] = v;
        }
        hs[i] = v;
    }
    __syncthreads();
#pragma unroll
    for (int r = 0; r < 16; r++) {
        int j = threadIdx.x + r * 256;
        int ln = j >> 7, col = j & 127;
        int node = base + ln;
        if (node < n) {
            float acc = b2[col];
            const float* h = &hs[ln * 64];
#pragma unroll
            for (int k = 0; k < 64; k++) acc += h[k] * Ws[k * 128 + col];
            g_tmp2[(size_t)node * 128 + col] = acc;
        }
    }
}

// ---------------------------------------------------------------------------
// Layer-2 edges. Warp per edge, register weights (16 ull), direct x LDG,
// prefetch, no smem x, no syncs in loop.
// Thread (b=t>>2, q=t&3): outputs o = b*16 + q*4 .. +3.
// ---------------------------------------------------------------------------
__global__ void __launch_bounds__(256) k_edge2s(const float* __restrict__ w2) {
    if ((int)blockIdx.x >= g_bpre[NREL]) return;
    int info = g_blockrel[blockIdx.x];
    int r = info >> 16, ci = info & 0xFFFF;
    int ebase = g_offs[r] + ci * CHUNK;
    int cnt = min(CHUNK, g_offs[r + 1] - ebase);

    __shared__ int ssrc[CHUNK];
    __shared__ int sdst[CHUNK];
    __shared__ float snorm[CHUNK];

    int tid = threadIdx.x;
    int w = tid >> 5, t = tid & 31;
    int b = t >> 2, q = t & 3;

    // per-thread weights: w2[r*1024 + b*128 + i*16 + q*4 .. +3], i=0..7
    const float* wp = w2 + (size_t)r * 1024 + b * 128 + q * 4;
    ull wlo[8], whi[8];
#pragma unroll
    for (int i = 0; i < 8; i++) {
        float4 w4 = *(const float4*)(wp + i * 16);
        wlo[i] = pack2(w4.x, w4.y);
        whi[i] = pack2(w4.z, w4.w);
    }

    if (tid < cnt) {
        ssrc[tid] = g_src_s[ebase + tid];
        sdst[tid] = g_dst_s[ebase + tid];
        snorm[tid] = g_norm_s[ebase + tid];
    }
    __syncthreads();

    int jc = w;                                // 8 edges per iteration
    bool vc = (jc < cnt);
    int jcc = vc ? jc : 0;
    const float4* xp = (const float4*)(g_h1 + (size_t)ssrc[jcc] * 64 + b * 8);
    float4 xA = xp[0], xB = xp[1];

    for (int it = 0; it < 32; it++) {
        int jn = jc + 8;
        bool vn = (jn < cnt);
        int jnn = vn ? jn : 0;
        const float4* xq = (const float4*)(g_h1 + (size_t)ssrc[jnn] * 64 + b * 8);
        float4 yA = xq[0], yB = xq[1];

        if (vc) {
            float nm = snorm[jc];
            ull a0 = 0ULL, a1 = 0ULL;
            ull xx;
            xx = pack2(xA.x, xA.x); fma2(a0, xx, wlo[0]); fma2(a1, xx, whi[0]);
            xx = pack2(xA.y, xA.y); fma2(a0, xx, wlo[1]); fma2(a1, xx, whi[1]);
            xx = pack2(xA.z, xA.z); fma2(a0, xx, wlo[2]); fma2(a1, xx, whi[2]);
            xx = pack2(xA.w, xA.w); fma2(a0, xx, wlo[3]); fma2(a1, xx, whi[3]);
            xx = pack2(xB.x, xB.x); fma2(a0, xx, wlo[4]); fma2(a1, xx, whi[4]);
            xx = pack2(xB.y, xB.y); fma2(a0, xx, wlo[5]); fma2(a1, xx, whi[5]);
            xx = pack2(xB.z, xB.z); fma2(a0, xx, wlo[6]); fma2(a1, xx, whi[6]);
            xx = pack2(xB.w, xB.w); fma2(a0, xx, wlo[7]); fma2(a1, xx, whi[7]);
            ull nn = pack2(nm, nm);
            mul2(a0, nn); mul2(a1, nn);
            float f0, f1, f2, f3;
            unpack2(a0, f0, f1);
            unpack2(a1, f2, f3);
            red4(&g_tmp2[(size_t)sdst[jc] * 128 + b * 16 + q * 4], f0, f1, f2, f3);
        }
        xA = yA; xB = yB; jc = jn; vc = vn;
    }
}

// ---------------------------------------------------------------------------
// Final: out = m + sqrt(softplus(raw_v)+1e-8) * eps   (float4 vectorized)
// ---------------------------------------------------------------------------
__global__ void k_final(const float* __restrict__ eps,
                        float* __restrict__ out,
                        int n) {
    int gi = blockIdx.x * blockDim.x + threadIdx.x;
    int total = n * 16;
    if (gi < total) {
        int node = gi >> 4, c4 = gi & 15;
        const float4* t2 = (const float4*)g_tmp2;
        float4 m = t2[(size_t)node * 32 + c4];
        float4 rv = t2[(size_t)node * 32 + 16 + c4];
        float4 e = ((const float4*)eps)[gi];
        float4 o;
        float sp;
        sp = (rv.x > 20.f) ? rv.x : log1pf(expf(rv.x)); o.x = m.x + sqrtf(sp + 1e-8f) * e.x;
        sp = (rv.y > 20.f) ? rv.y : log1pf(expf(rv.y)); o.y = m.y + sqrtf(sp + 1e-8f) * e.y;
        sp = (rv.z > 20.f) ? rv.z : log1pf(expf(rv.z)); o.z = m.z + sqrtf(sp + 1e-8f) * e.z;
        sp = (rv.w > 20.f) ? rv.w : log1pf(expf(rv.w)); o.w = m.w + sqrtf(sp + 1e-8f) * e.w;
        ((float4*)out)[gi] = o;
    }
}

// ---------------------------------------------------------------------------
extern "C" void kernel_launch(void* const* d_in, const int* in_sizes, int n_in,
                              void* d_out, int out_size) {
    const float* emb   = (const float*)d_in[0];
    const float* norm  = (const float*)d_in[1];
    const float* eps   = (const float*)d_in[2];
    const float* w1    = (const float*)d_in[3];
    const float* lw1   = (const float*)d_in[4];
    const float* b1    = (const float*)d_in[5];
    const float* w2    = (const float*)d_in[6];
    const float* lw2   = (const float*)d_in[7];
    const float* b2    = (const float*)d_in[8];
    const int*   h_ids = (const int*)d_in[9];
    const int*   src   = (const int*)d_in[10];
    const int*   dst   = (const int*)d_in[11];
    const int*   rel   = (const int*)d_in[12];

    int n  = in_sizes[9];
    int ne = in_sizes[10];

    int maxb = ne / CHUNK + NREL + 1;
    int sblocks = (ne + SCHUNK - 1) / SCHUNK;

    k_zero<<<1, 256>>>();
    k_hist<<<96, 256>>>(rel, ne);
    k_scan<<<1, 256>>>();
    k_blockmap<<<NREL, 32>>>();
    k_scatter<<<sblocks, 256>>>(rel, src, dst, norm, h_ids, ne);

    k_loop1<<<(n + 31) / 32, 256>>>(emb, h_ids, lw1, b1, n);
    k_edge1s<<<maxb, 256>>>(emb, w1);
    k_loop2<<<(n + 31) / 32, 256>>>(lw2, b2, n);
    k_edge2s<<<maxb, 256>>>(w2);
    k_final<<<(n * 16 + 255) / 256, 256>>>(eps, (float*)d_out, n);
}

// round 6
// speedup vs baseline: 3.0918x; 1.2413x over previous
#include <cuda_runtime.h>
#include <math.h>

#define MAXN 50000
#define MAXE 400000
#define NREL 200
#define CHUNK 256
#define MAXB 4096
#define SCHUNK 1024

typedef unsigned long long ull;

// Scratch (static device globals — no allocation allowed)
__device__ __align__(16) float g_tmp1[MAXN * 64];
__device__ __align__(16) float g_h1[MAXN * 64];
__device__ __align__(16) float g_tmp2[MAXN * 128];

// sort scratch (g_hist/g_cursor start zero; k_scan re-zeroes them each launch)
__device__ int g_hist[NREL];
__device__ int g_cursor[NREL];
__device__ int g_offs[NREL + 1];
__device__ int g_bpre[NREL + 1];
__device__ int g_blockrel[MAXB];
__device__ __align__(16) int4 g_edge_s[MAXE];   // {src_hid, dst, norm_bits, 0}

// ---------------------------------------------------------------------------
// f32x2 packed-math helpers
// ---------------------------------------------------------------------------
__device__ __forceinline__ ull pack2(float x, float y) {
    ull r; asm("mov.b64 %0, {%1,%2};" : "=l"(r) : "f"(x), "f"(y)); return r;
}
__device__ __forceinline__ void unpack2(ull v, float& x, float& y) {
    asm("mov.b64 {%0,%1}, %2;" : "=f"(x), "=f"(y) : "l"(v));
}
__device__ __forceinline__ void fma2(ull& acc, ull a, ull b) {
    asm("fma.rn.f32x2 %0, %1, %2, %0;" : "+l"(acc) : "l"(a), "l"(b));
}
__device__ __forceinline__ void mul2(ull& a, ull b) {
    asm("mul.rn.f32x2 %0, %1, %2;" : "+l"(a) : "l"(a), "l"(b));
}
__device__ __forceinline__ void red4(float* addr, float a, float b, float c, float d) {
    asm volatile("red.global.add.v4.f32 [%0], {%1,%2,%3,%4};"
                 :: "l"(addr), "f"(a), "f"(b), "f"(c), "f"(d) : "memory");
}

// ---------------------------------------------------------------------------
// Sort pipeline
// ---------------------------------------------------------------------------
__global__ void k_hist(const int* __restrict__ rel, int ne) {
    __shared__ int sh[NREL];
    for (int i = threadIdx.x; i < NREL; i += blockDim.x) sh[i] = 0;
    __syncthreads();
    int stride = gridDim.x * blockDim.x;
    for (int e = blockIdx.x * blockDim.x + threadIdx.x; e < ne; e += stride)
        atomicAdd(&sh[rel[e]], 1);
    __syncthreads();
    for (int i = threadIdx.x; i < NREL; i += blockDim.x)
        if (sh[i]) atomicAdd(&g_hist[i], sh[i]);
}

// Fused: scan of hist -> offs/bpre, reset hist+cursor, fill blockrel table.
__global__ void k_scan() {
    __shared__ int sh[256], sb[256];
    int t = threadIdx.x;
    int h = (t < NREL) ? g_hist[t] : 0;
    if (t < NREL) { g_hist[t] = 0; g_cursor[t] = 0; }   // reset for this/next launch
    int b = (h + CHUNK - 1) / CHUNK;
    sh[t] = h; sb[t] = b;
    __syncthreads();
    for (int off = 1; off < 256; off <<= 1) {
        int vh = 0, vb = 0;
        if (t >= off) { vh = sh[t - off]; vb = sb[t - off]; }
        __syncthreads();
        sh[t] += vh; sb[t] += vb;
        __syncthreads();
    }
    if (t < NREL) { g_offs[t + 1] = sh[t]; g_bpre[t + 1] = sb[t]; }
    if (t == 0) { g_offs[0] = 0; g_bpre[0] = 0; }
    __syncthreads();
    int totalB = sb[NREL - 1];
    // fill block -> (rel, chunk) via smem binary search on inclusive scan sb
    for (int blk = t; blk < totalB; blk += 256) {
        int lo = 0, hi = NREL - 1;
        while (lo < hi) {
            int mid = (lo + hi) >> 1;
            if (sb[mid] > blk) hi = mid; else lo = mid + 1;
        }
        int prev = lo ? sb[lo - 1] : 0;
        g_blockrel[blk] = (lo << 16) | (blk - prev);
    }
}

// Two-level scatter: smem local ranks + one global atomic per (block, rel).
// Writes one int4 record per edge.
__global__ void k_scatter(const int* __restrict__ rel,
                          const int* __restrict__ src,
                          const int* __restrict__ dst,
                          const float* __restrict__ norm,
                          const int* __restrict__ h_ids,
                          int ne) {
    __shared__ int cur[NREL];
    __shared__ int base[NREL];
    for (int i = threadIdx.x; i < NREL; i += 256) cur[i] = 0;
    __syncthreads();
    int start = blockIdx.x * SCHUNK;
    int lr[4], lrank[4];
#pragma unroll
    for (int it = 0; it < 4; it++) {
        int e = start + it * 256 + threadIdx.x;
        if (e < ne) {
            int r = rel[e];
            lr[it] = r;
            lrank[it] = atomicAdd(&cur[r], 1);
        }
    }
    __syncthreads();
    for (int i = threadIdx.x; i < NREL; i += 256) {
        int c = cur[i];
        base[i] = c ? atomicAdd(&g_cursor[i], c) : 0;
    }
    __syncthreads();
#pragma unroll
    for (int it = 0; it < 4; it++) {
        int e = start + it * 256 + threadIdx.x;
        if (e < ne) {
            int r = lr[it];
            int pos = g_offs[r] + base[r] + lrank[it];
            int4 rec;
            rec.x = h_ids[src[e]];
            rec.y = dst[e];
            rec.z = __float_as_int(norm[e]);
            rec.w = 0;
            g_edge_s[pos] = rec;
        }
    }
}

// ---------------------------------------------------------------------------
// tmp1[n] = b1 + feat[n] @ loop_w1 (64x64). 32 nodes/block.
// Thread owns fixed col; weight column (64f) in registers.
// ---------------------------------------------------------------------------
__global__ void __launch_bounds__(256) k_loop1(const float* __restrict__ emb,
                                               const int* __restrict__ h_ids,
                                               const float* __restrict__ W,
                                               const float* __restrict__ b1,
                                               int n) {
    __shared__ float fs[32 * 64];
    int tid = threadIdx.x;
    int col = tid & 63;
    int grp = tid >> 6;   // 0..3
    float wreg[64];
#pragma unroll
    for (int k = 0; k < 64; k++) wreg[k] = W[k * 64 + col];
    float bias = b1[col];
    int base = blockIdx.x * 32;
    for (int i = tid; i < 2048; i += 256) {
        int node = base + (i >> 6);
        fs[i] = (node < n) ? emb[(size_t)h_ids[node] * 64 + (i & 63)] : 0.f;
    }
    __syncthreads();
#pragma unroll
    for (int r = 0; r < 8; r++) {
        int nl = grp + 4 * r;
        int node = base + nl;
        if (node < n) {
            float acc = bias;
            const float* f = &fs[nl * 64];
#pragma unroll
            for (int k = 0; k < 64; k++) acc += f[k] * wreg[k];
            g_tmp1[(size_t)node * 64 + col] = acc;
        }
    }
}

// ---------------------------------------------------------------------------
// Layer-1 edges. 16 threads/edge, register weights, int4 edge records,
// direct x LDG with prefetch, no syncs in loop.
// ---------------------------------------------------------------------------
__global__ void __launch_bounds__(256) k_edge1s(const float* __restrict__ emb,
                                                const float* __restrict__ w1) {
    if ((int)blockIdx.x >= g_bpre[NREL]) return;
    int info = g_blockrel[blockIdx.x];
    int r = info >> 16, ci = info & 0xFFFF;
    int ebase = g_offs[r] + ci * CHUNK;
    int cnt = min(CHUNK, g_offs[r + 1] - ebase);

    __shared__ __align__(16) int4 sedge[CHUNK];

    int tid = threadIdx.x;
    int u = tid & 15;
    int es = (tid >> 4) & 1;
    int w = tid >> 5;
    int b = u >> 1, q = u & 1;

    const float4* wrow = (const float4*)(w1 + (size_t)r * 512 + b * 64 + q * 4);
    ull wlo[8], whi[8];
#pragma unroll
    for (int i = 0; i < 8; i++) {
        float4 w4 = wrow[i * 2];
        wlo[i] = pack2(w4.x, w4.y);
        whi[i] = pack2(w4.z, w4.w);
    }

    if (tid < cnt) sedge[tid] = g_edge_s[ebase + tid];
    __syncthreads();

    int jc = w * 2 + es;
    bool vc = (jc < cnt);
    int4 rc = vc ? sedge[jc] : make_int4(0, 0, 0, 0);
    const float4* xp = (const float4*)(emb + (size_t)rc.x * 64 + b * 8);
    float4 xA = xp[0], xB = xp[1];

    for (int it = 0; it < 16; it++) {
        int jn = jc + 16;
        bool vn = (jn < cnt);
        int4 rn = vn ? sedge[jn] : make_int4(0, 0, 0, 0);
        const float4* xq = (const float4*)(emb + (size_t)rn.x * 64 + b * 8);
        float4 yA = xq[0], yB = xq[1];

        if (vc) {
            float nm = __int_as_float(rc.z);
            ull a0 = 0ULL, a1 = 0ULL;
            ull xx;
            xx = pack2(xA.x, xA.x); fma2(a0, xx, wlo[0]); fma2(a1, xx, whi[0]);
            xx = pack2(xA.y, xA.y); fma2(a0, xx, wlo[1]); fma2(a1, xx, whi[1]);
            xx = pack2(xA.z, xA.z); fma2(a0, xx, wlo[2]); fma2(a1, xx, whi[2]);
            xx = pack2(xA.w, xA.w); fma2(a0, xx, wlo[3]); fma2(a1, xx, whi[3]);
            xx = pack2(xB.x, xB.x); fma2(a0, xx, wlo[4]); fma2(a1, xx, whi[4]);
            xx = pack2(xB.y, xB.y); fma2(a0, xx, wlo[5]); fma2(a1, xx, whi[5]);
            xx = pack2(xB.z, xB.z); fma2(a0, xx, wlo[6]); fma2(a1, xx, whi[6]);
            xx = pack2(xB.w, xB.w); fma2(a0, xx, wlo[7]); fma2(a1, xx, whi[7]);
            ull nn = pack2(nm, nm);
            mul2(a0, nn); mul2(a1, nn);
            float f0, f1, f2, f3;
            unpack2(a0, f0, f1);
            unpack2(a1, f2, f3);
            red4(&g_tmp1[(size_t)rc.y * 64 + b * 8 + q * 4], f0, f1, f2, f3);
        }
        xA = yA; xB = yB; jc = jn; vc = vn; rc = rn;
    }
}

// ---------------------------------------------------------------------------
// h1 = relu(tmp1); tmp2 = b2 + h1 @ loop_w2 (64x128). 32 nodes/block.
// Thread owns fixed col; weight column (64f) in registers.
// ---------------------------------------------------------------------------
__global__ void __launch_bounds__(256) k_loop2(const float* __restrict__ W2,
                                               const float* __restrict__ b2,
                                               int n) {
    __shared__ float hs[32 * 64];
    int tid = threadIdx.x;
    int col = tid & 127;
    int grp = tid >> 7;   // 0..1
    float wreg[64];
#pragma unroll
    for (int k = 0; k < 64; k++) wreg[k] = W2[k * 128 + col];
    float bias = b2[col];
    int base = blockIdx.x * 32;
    for (int i = tid; i < 2048; i += 256) {
        int node = base + (i >> 6);
        float v = 0.f;
        if (node < n) {
            v = g_tmp1[(size_t)node * 64 + (i & 63)];
            v = v > 0.f ? v : 0.f;
            g_h1[(size_t)node * 64 + (i & 63)] = v;
        }
        hs[i] = v;
    }
    __syncthreads();
#pragma unroll
    for (int r = 0; r < 16; r++) {
        int nl = grp + 2 * r;
        int node = base + nl;
        if (node < n) {
            float acc = bias;
            const float* h = &hs[nl * 64];
#pragma unroll
            for (int k = 0; k < 64; k++) acc += h[k] * wreg[k];
            g_tmp2[(size_t)node * 128 + col] = acc;
        }
    }
}

// ---------------------------------------------------------------------------
// Layer-2 edges. Warp per edge, register weights, int4 records, direct x LDG.
// ---------------------------------------------------------------------------
__global__ void __launch_bounds__(256) k_edge2s(const float* __restrict__ w2) {
    if ((int)blockIdx.x >= g_bpre[NREL]) return;
    int info = g_blockrel[blockIdx.x];
    int r = info >> 16, ci = info & 0xFFFF;
    int ebase = g_offs[r] + ci * CHUNK;
    int cnt = min(CHUNK, g_offs[r + 1] - ebase);

    __shared__ __align__(16) int4 sedge[CHUNK];

    int tid = threadIdx.x;
    int w = tid >> 5, t = tid & 31;
    int b = t >> 2, q = t & 3;

    const float* wp = w2 + (size_t)r * 1024 + b * 128 + q * 4;
    ull wlo[8], whi[8];
#pragma unroll
    for (int i = 0; i < 8; i++) {
        float4 w4 = *(const float4*)(wp + i * 16);
        wlo[i] = pack2(w4.x, w4.y);
        whi[i] = pack2(w4.z, w4.w);
    }

    if (tid < cnt) sedge[tid] = g_edge_s[ebase + tid];
    __syncthreads();

    int jc = w;
    bool vc = (jc < cnt);
    int4 rc = vc ? sedge[jc] : make_int4(0, 0, 0, 0);
    const float4* xp = (const float4*)(g_h1 + (size_t)rc.x * 64 + b * 8);
    float4 xA = xp[0], xB = xp[1];

    for (int it = 0; it < 32; it++) {
        int jn = jc + 8;
        bool vn = (jn < cnt);
        int4 rn = vn ? sedge[jn] : make_int4(0, 0, 0, 0);
        const float4* xq = (const float4*)(g_h1 + (size_t)rn.x * 64 + b * 8);
        float4 yA = xq[0], yB = xq[1];

        if (vc) {
            float nm = __int_as_float(rc.z);
            ull a0 = 0ULL, a1 = 0ULL;
            ull xx;
            xx = pack2(xA.x, xA.x); fma2(a0, xx, wlo[0]); fma2(a1, xx, whi[0]);
            xx = pack2(xA.y, xA.y); fma2(a0, xx, wlo[1]); fma2(a1, xx, whi[1]);
            xx = pack2(xA.z, xA.z); fma2(a0, xx, wlo[2]); fma2(a1, xx, whi[2]);
            xx = pack2(xA.w, xA.w); fma2(a0, xx, wlo[3]); fma2(a1, xx, whi[3]);
            xx = pack2(xB.x, xB.x); fma2(a0, xx, wlo[4]); fma2(a1, xx, whi[4]);
            xx = pack2(xB.y, xB.y); fma2(a0, xx, wlo[5]); fma2(a1, xx, whi[5]);
            xx = pack2(xB.z, xB.z); fma2(a0, xx, wlo[6]); fma2(a1, xx, whi[6]);
            xx = pack2(xB.w, xB.w); fma2(a0, xx, wlo[7]); fma2(a1, xx, whi[7]);
            ull nn = pack2(nm, nm);
            mul2(a0, nn); mul2(a1, nn);
            float f0, f1, f2, f3;
            unpack2(a0, f0, f1);
            unpack2(a1, f2, f3);
            red4(&g_tmp2[(size_t)rc.y * 128 + b * 16 + q * 4], f0, f1, f2, f3);
        }
        xA = yA; xB = yB; jc = jn; vc = vn; rc = rn;
    }
}

// ---------------------------------------------------------------------------
// Final: out = m + sqrt(softplus(raw_v)+1e-8) * eps   (float4 vectorized)
// ---------------------------------------------------------------------------
__global__ void k_final(const float* __restrict__ eps,
                        float* __restrict__ out,
                        int n) {
    int gi = blockIdx.x * blockDim.x + threadIdx.x;
    int total = n * 16;
    if (gi < total) {
        int node = gi >> 4, c4 = gi & 15;
        const float4* t2 = (const float4*)g_tmp2;
        float4 m = t2[(size_t)node * 32 + c4];
        float4 rv = t2[(size_t)node * 32 + 16 + c4];
        float4 e = ((const float4*)eps)[gi];
        float4 o;
        float sp;
        sp = (rv.x > 20.f) ? rv.x : log1pf(expf(rv.x)); o.x = m.x + sqrtf(sp + 1e-8f) * e.x;
        sp = (rv.y > 20.f) ? rv.y : log1pf(expf(rv.y)); o.y = m.y + sqrtf(sp + 1e-8f) * e.y;
        sp = (rv.z > 20.f) ? rv.z : log1pf(expf(rv.z)); o.z = m.z + sqrtf(sp + 1e-8f) * e.z;
        sp = (rv.w > 20.f) ? rv.w : log1pf(expf(rv.w)); o.w = m.w + sqrtf(sp + 1e-8f) * e.w;
        ((float4*)out)[gi] = o;
    }
}

// ---------------------------------------------------------------------------
extern "C" void kernel_launch(void* const* d_in, const int* in_sizes, int n_in,
                              void* d_out, int out_size) {
    const float* emb   = (const float*)d_in[0];
    const float* norm  = (const float*)d_in[1];
    const float* eps   = (const float*)d_in[2];
    const float* w1    = (const float*)d_in[3];
    const float* lw1   = (const float*)d_in[4];
    const float* b1    = (const float*)d_in[5];
    const float* w2    = (const float*)d_in[6];
    const float* lw2   = (const float*)d_in[7];
    const float* b2    = (const float*)d_in[8];
    const int*   h_ids = (const int*)d_in[9];
    const int*   src   = (const int*)d_in[10];
    const int*   dst   = (const int*)d_in[11];
    const int*   rel   = (const int*)d_in[12];

    int n  = in_sizes[9];
    int ne = in_sizes[10];

    int maxb = ne / CHUNK + NREL + 1;
    int sblocks = (ne + SCHUNK - 1) / SCHUNK;

    k_hist<<<96, 256>>>(rel, ne);
    k_scan<<<1, 256>>>();
    k_scatter<<<sblocks, 256>>>(rel, src, dst, norm, h_ids, ne);

    k_loop1<<<(n + 31) / 32, 256>>>(emb, h_ids, lw1, b1, n);
    k_edge1s<<<maxb, 256>>>(emb, w1);
    k_loop2<<<(n + 31) / 32, 256>>>(lw2, b2, n);
    k_edge2s<<<maxb, 256>>>(w2);
    k_final<<<(n * 16 + 255) / 256, 256>>>(eps, (float*)d_out, n);
}

// round 7
// speedup vs baseline: 3.3985x; 1.0992x over previous
#include <cuda_runtime.h>
#include <math.h>

#define MAXN 50000
#define MAXE 400000
#define NREL 200
#define CHUNK 256
#define MAXB 4096
#define SCHUNK 1024

typedef unsigned long long ull;

// Scratch (static device globals — no allocation allowed)
__device__ __align__(16) float g_tmp1[MAXN * 64];
__device__ __align__(16) float g_h1[MAXN * 64];
__device__ __align__(16) float g_tmp2[MAXN * 128];

// sort scratch (g_hist/g_cursor start zero; k_scan re-zeroes them each launch)
__device__ int g_hist[NREL];
__device__ int g_cursor[NREL];
__device__ int g_offs[NREL + 1];
__device__ int g_bpre[NREL + 1];
__device__ int g_blockrel[MAXB];
__device__ __align__(16) int4 g_edge_s[MAXE];   // {src_hid, dst, norm_bits, 0}

// ---------------------------------------------------------------------------
// f32x2 packed-math helpers
// ---------------------------------------------------------------------------
__device__ __forceinline__ ull pack2(float x, float y) {
    ull r; asm("mov.b64 %0, {%1,%2};" : "=l"(r) : "f"(x), "f"(y)); return r;
}
__device__ __forceinline__ void unpack2(ull v, float& x, float& y) {
    asm("mov.b64 {%0,%1}, %2;" : "=f"(x), "=f"(y) : "l"(v));
}
__device__ __forceinline__ void fma2(ull& acc, ull a, ull b) {
    asm("fma.rn.f32x2 %0, %1, %2, %0;" : "+l"(acc) : "l"(a), "l"(b));
}
__device__ __forceinline__ void mul2(ull& a, ull b) {
    asm("mul.rn.f32x2 %0, %1, %2;" : "+l"(a) : "l"(a), "l"(b));
}
__device__ __forceinline__ void red4(float* addr, float a, float b, float c, float d) {
    asm volatile("red.global.add.v4.f32 [%0], {%1,%2,%3,%4};"
                 :: "l"(addr), "f"(a), "f"(b), "f"(c), "f"(d) : "memory");
}

// ---------------------------------------------------------------------------
// Sort pipeline
// ---------------------------------------------------------------------------
__global__ void k_hist(const int* __restrict__ rel, int ne) {
    __shared__ int sh[NREL];
    for (int i = threadIdx.x; i < NREL; i += blockDim.x) sh[i] = 0;
    __syncthreads();
    int stride = gridDim.x * blockDim.x;
    for (int e = blockIdx.x * blockDim.x + threadIdx.x; e < ne; e += stride)
        atomicAdd(&sh[rel[e]], 1);
    __syncthreads();
    for (int i = threadIdx.x; i < NREL; i += blockDim.x)
        if (sh[i]) atomicAdd(&g_hist[i], sh[i]);
}

// Fused: scan of hist -> offs/bpre, reset hist+cursor, fill blockrel table.
__global__ void k_scan() {
    __shared__ int sh[256], sb[256];
    int t = threadIdx.x;
    int h = (t < NREL) ? g_hist[t] : 0;
    if (t < NREL) { g_hist[t] = 0; g_cursor[t] = 0; }
    int b = (h + CHUNK - 1) / CHUNK;
    sh[t] = h; sb[t] = b;
    __syncthreads();
    for (int off = 1; off < 256; off <<= 1) {
        int vh = 0, vb = 0;
        if (t >= off) { vh = sh[t - off]; vb = sb[t - off]; }
        __syncthreads();
        sh[t] += vh; sb[t] += vb;
        __syncthreads();
    }
    if (t < NREL) { g_offs[t + 1] = sh[t]; g_bpre[t + 1] = sb[t]; }
    if (t == 0) { g_offs[0] = 0; g_bpre[0] = 0; }
    __syncthreads();
    int totalB = sb[NREL - 1];
    for (int blk = t; blk < totalB; blk += 256) {
        int lo = 0, hi = NREL - 1;
        while (lo < hi) {
            int mid = (lo + hi) >> 1;
            if (sb[mid] > blk) hi = mid; else lo = mid + 1;
        }
        int prev = lo ? sb[lo - 1] : 0;
        g_blockrel[blk] = (lo << 16) | (blk - prev);
    }
}

// Two-level scatter: smem local ranks + one global atomic per (block, rel).
__global__ void k_scatter(const int* __restrict__ rel,
                          const int* __restrict__ src,
                          const int* __restrict__ dst,
                          const float* __restrict__ norm,
                          const int* __restrict__ h_ids,
                          int ne) {
    __shared__ int cur[NREL];
    __shared__ int base[NREL];
    for (int i = threadIdx.x; i < NREL; i += 256) cur[i] = 0;
    __syncthreads();
    int start = blockIdx.x * SCHUNK;
    int lr[4], lrank[4];
#pragma unroll
    for (int it = 0; it < 4; it++) {
        int e = start + it * 256 + threadIdx.x;
        if (e < ne) {
            int r = rel[e];
            lr[it] = r;
            lrank[it] = atomicAdd(&cur[r], 1);
        }
    }
    __syncthreads();
    for (int i = threadIdx.x; i < NREL; i += 256) {
        int c = cur[i];
        base[i] = c ? atomicAdd(&g_cursor[i], c) : 0;
    }
    __syncthreads();
#pragma unroll
    for (int it = 0; it < 4; it++) {
        int e = start + it * 256 + threadIdx.x;
        if (e < ne) {
            int r = lr[it];
            int pos = g_offs[r] + base[r] + lrank[it];
            int4 rec;
            rec.x = h_ids[src[e]];
            rec.y = dst[e];
            rec.z = __float_as_int(norm[e]);
            rec.w = 0;
            g_edge_s[pos] = rec;
        }
    }
}

// ---------------------------------------------------------------------------
// tmp1 = b1 + feat @ loop_w1 (64x64). Register-tiled f32x2 GEMM.
// Block: 64 nodes x 64 cols. Thread: 4 nodes x 4 cols. 256 threads.
// ---------------------------------------------------------------------------
__global__ void __launch_bounds__(256) k_loop1(const float* __restrict__ emb,
                                               const int* __restrict__ h_ids,
                                               const float* __restrict__ W,
                                               const float* __restrict__ b1,
                                               int n) {
    __shared__ float Ws[64 * 64];
    __shared__ float Xs[64][68];
    int tid = threadIdx.x;
    for (int i = tid; i < 4096; i += 256) Ws[i] = W[i];
    int base = blockIdx.x * 64;
    for (int i = tid; i < 4096; i += 256) {
        int nl = i >> 6, c = i & 63;
        int node = base + nl;
        Xs[nl][c] = (node < n) ? emb[(size_t)h_ids[node] * 64 + c] : 0.f;
    }
    __syncthreads();

    int ty = tid >> 4, tx = tid & 15;     // ty: node group, tx: col group
    int c0 = tx * 4;
    ull acc[4][2];
    {
        ull blo = pack2(b1[c0], b1[c0 + 1]);
        ull bhi = pack2(b1[c0 + 2], b1[c0 + 3]);
#pragma unroll
        for (int i = 0; i < 4; i++) { acc[i][0] = blo; acc[i][1] = bhi; }
    }

#pragma unroll
    for (int k4 = 0; k4 < 16; k4++) {
        float4 xv[4], wv[4];
#pragma unroll
        for (int i = 0; i < 4; i++)
            xv[i] = *(const float4*)&Xs[ty * 4 + i][k4 * 4];
#pragma unroll
        for (int j = 0; j < 4; j++)
            wv[j] = *(const float4*)&Ws[(k4 * 4 + j) * 64 + c0];
#pragma unroll
        for (int j = 0; j < 4; j++) {
            ull wlo = pack2(wv[j].x, wv[j].y);
            ull whi = pack2(wv[j].z, wv[j].w);
#pragma unroll
            for (int i = 0; i < 4; i++) {
                float xs = ((const float*)&xv[i])[j];
                ull xx = pack2(xs, xs);
                fma2(acc[i][0], xx, wlo);
                fma2(acc[i][1], xx, whi);
            }
        }
    }
#pragma unroll
    for (int i = 0; i < 4; i++) {
        int node = base + ty * 4 + i;
        if (node < n) {
            float4 o;
            unpack2(acc[i][0], o.x, o.y);
            unpack2(acc[i][1], o.z, o.w);
            *(float4*)&g_tmp1[(size_t)node * 64 + c0] = o;
        }
    }
}

// ---------------------------------------------------------------------------
// Layer-1 edges. 16 threads/edge, register weights, int4 edge records,
// direct x LDG with prefetch, no syncs in loop.
// ---------------------------------------------------------------------------
__global__ void __launch_bounds__(256) k_edge1s(const float* __restrict__ emb,
                                                const float* __restrict__ w1) {
    if ((int)blockIdx.x >= g_bpre[NREL]) return;
    int info = g_blockrel[blockIdx.x];
    int r = info >> 16, ci = info & 0xFFFF;
    int ebase = g_offs[r] + ci * CHUNK;
    int cnt = min(CHUNK, g_offs[r + 1] - ebase);

    __shared__ __align__(16) int4 sedge[CHUNK];

    int tid = threadIdx.x;
    int u = tid & 15;
    int es = (tid >> 4) & 1;
    int w = tid >> 5;
    int b = u >> 1, q = u & 1;

    const float4* wrow = (const float4*)(w1 + (size_t)r * 512 + b * 64 + q * 4);
    ull wlo[8], whi[8];
#pragma unroll
    for (int i = 0; i < 8; i++) {
        float4 w4 = wrow[i * 2];
        wlo[i] = pack2(w4.x, w4.y);
        whi[i] = pack2(w4.z, w4.w);
    }

    if (tid < cnt) sedge[tid] = g_edge_s[ebase + tid];
    __syncthreads();

    int jc = w * 2 + es;
    bool vc = (jc < cnt);
    int4 rc = vc ? sedge[jc] : make_int4(0, 0, 0, 0);
    const float4* xp = (const float4*)(emb + (size_t)rc.x * 64 + b * 8);
    float4 xA = xp[0], xB = xp[1];

    for (int it = 0; it < 16; it++) {
        int jn = jc + 16;
        bool vn = (jn < cnt);
        int4 rn = vn ? sedge[jn] : make_int4(0, 0, 0, 0);
        const float4* xq = (const float4*)(emb + (size_t)rn.x * 64 + b * 8);
        float4 yA = xq[0], yB = xq[1];

        if (vc) {
            float nm = __int_as_float(rc.z);
            ull a0 = 0ULL, a1 = 0ULL;
            ull xx;
            xx = pack2(xA.x, xA.x); fma2(a0, xx, wlo[0]); fma2(a1, xx, whi[0]);
            xx = pack2(xA.y, xA.y); fma2(a0, xx, wlo[1]); fma2(a1, xx, whi[1]);
            xx = pack2(xA.z, xA.z); fma2(a0, xx, wlo[2]); fma2(a1, xx, whi[2]);
            xx = pack2(xA.w, xA.w); fma2(a0, xx, wlo[3]); fma2(a1, xx, whi[3]);
            xx = pack2(xB.x, xB.x); fma2(a0, xx, wlo[4]); fma2(a1, xx, whi[4]);
            xx = pack2(xB.y, xB.y); fma2(a0, xx, wlo[5]); fma2(a1, xx, whi[5]);
            xx = pack2(xB.z, xB.z); fma2(a0, xx, wlo[6]); fma2(a1, xx, whi[6]);
            xx = pack2(xB.w, xB.w); fma2(a0, xx, wlo[7]); fma2(a1, xx, whi[7]);
            ull nn = pack2(nm, nm);
            mul2(a0, nn); mul2(a1, nn);
            float f0, f1, f2, f3;
            unpack2(a0, f0, f1);
            unpack2(a1, f2, f3);
            red4(&g_tmp1[(size_t)rc.y * 64 + b * 8 + q * 4], f0, f1, f2, f3);
        }
        xA = yA; xB = yB; jc = jn; vc = vn; rc = rn;
    }
}

// ---------------------------------------------------------------------------
// h1 = relu(tmp1); tmp2 = b2 + h1 @ loop_w2 (64x128). Register-tiled f32x2.
// Block: 32 nodes x 128 cols. Thread: 4 nodes x 4 cols. 256 threads.
// ---------------------------------------------------------------------------
__global__ void __launch_bounds__(256) k_loop2(const float* __restrict__ W2,
                                               const float* __restrict__ b2,
                                               int n) {
    __shared__ float Ws[64 * 128];
    __shared__ float Xs[32][68];
    int tid = threadIdx.x;
    for (int i = tid; i < 8192; i += 256) Ws[i] = W2[i];
    int base = blockIdx.x * 32;
    for (int i = tid; i < 2048; i += 256) {
        int nl = i >> 6, c = i & 63;
        int node = base + nl;
        float v = 0.f;
        if (node < n) {
            v = g_tmp1[(size_t)node * 64 + c];
            v = v > 0.f ? v : 0.f;
            g_h1[(size_t)node * 64 + c] = v;
        }
        Xs[nl][c] = v;
    }
    __syncthreads();

    int ty = tid >> 5, tx = tid & 31;    // ty: node group (0..7), tx: col group (0..31)
    int c0 = tx * 4;
    ull acc[4][2];
    {
        ull blo = pack2(b2[c0], b2[c0 + 1]);
        ull bhi = pack2(b2[c0 + 2], b2[c0 + 3]);
#pragma unroll
        for (int i = 0; i < 4; i++) { acc[i][0] = blo; acc[i][1] = bhi; }
    }

#pragma unroll
    for (int k4 = 0; k4 < 16; k4++) {
        float4 xv[4], wv[4];
#pragma unroll
        for (int i = 0; i < 4; i++)
            xv[i] = *(const float4*)&Xs[ty * 4 + i][k4 * 4];
#pragma unroll
        for (int j = 0; j < 4; j++)
            wv[j] = *(const float4*)&Ws[(k4 * 4 + j) * 128 + c0];
#pragma unroll
        for (int j = 0; j < 4; j++) {
            ull wlo = pack2(wv[j].x, wv[j].y);
            ull whi = pack2(wv[j].z, wv[j].w);
#pragma unroll
            for (int i = 0; i < 4; i++) {
                float xs = ((const float*)&xv[i])[j];
                ull xx = pack2(xs, xs);
                fma2(acc[i][0], xx, wlo);
                fma2(acc[i][1], xx, whi);
            }
        }
    }
#pragma unroll
    for (int i = 0; i < 4; i++) {
        int node = base + ty * 4 + i;
        if (node < n) {
            float4 o;
            unpack2(acc[i][0], o.x, o.y);
            unpack2(acc[i][1], o.z, o.w);
            *(float4*)&g_tmp2[(size_t)node * 128 + c0] = o;
        }
    }
}

// ---------------------------------------------------------------------------
// Layer-2 edges. Warp per edge, register weights, int4 records, direct x LDG.
// ---------------------------------------------------------------------------
__global__ void __launch_bounds__(256) k_edge2s(const float* __restrict__ w2) {
    if ((int)blockIdx.x >= g_bpre[NREL]) return;
    int info = g_blockrel[blockIdx.x];
    int r = info >> 16, ci = info & 0xFFFF;
    int ebase = g_offs[r] + ci * CHUNK;
    int cnt = min(CHUNK, g_offs[r + 1] - ebase);

    __shared__ __align__(16) int4 sedge[CHUNK];

    int tid = threadIdx.x;
    int w = tid >> 5, t = tid & 31;
    int b = t >> 2, q = t & 3;

    const float* wp = w2 + (size_t)r * 1024 + b * 128 + q * 4;
    ull wlo[8], whi[8];
#pragma unroll
    for (int i = 0; i < 8; i++) {
        float4 w4 = *(const float4*)(wp + i * 16);
        wlo[i] = pack2(w4.x, w4.y);
        whi[i] = pack2(w4.z, w4.w);
    }

    if (tid < cnt) sedge[tid] = g_edge_s[ebase + tid];
    __syncthreads();

    int jc = w;
    bool vc = (jc < cnt);
    int4 rc = vc ? sedge[jc] : make_int4(0, 0, 0, 0);
    const float4* xp = (const float4*)(g_h1 + (size_t)rc.x * 64 + b * 8);
    float4 xA = xp[0], xB = xp[1];

    for (int it = 0; it < 32; it++) {
        int jn = jc + 8;
        bool vn = (jn < cnt);
        int4 rn = vn ? sedge[jn] : make_int4(0, 0, 0, 0);
        const float4* xq = (const float4*)(g_h1 + (size_t)rn.x * 64 + b * 8);
        float4 yA = xq[0], yB = xq[1];

        if (vc) {
            float nm = __int_as_float(rc.z);
            ull a0 = 0ULL, a1 = 0ULL;
            ull xx;
            xx = pack2(xA.x, xA.x); fma2(a0, xx, wlo[0]); fma2(a1, xx, whi[0]);
            xx = pack2(xA.y, xA.y); fma2(a0, xx, wlo[1]); fma2(a1, xx, whi[1]);
            xx = pack2(xA.z, xA.z); fma2(a0, xx, wlo[2]); fma2(a1, xx, whi[2]);
            xx = pack2(xA.w, xA.w); fma2(a0, xx, wlo[3]); fma2(a1, xx, whi[3]);
            xx = pack2(xB.x, xB.x); fma2(a0, xx, wlo[4]); fma2(a1, xx, whi[4]);
            xx = pack2(xB.y, xB.y); fma2(a0, xx, wlo[5]); fma2(a1, xx, whi[5]);
            xx = pack2(xB.z, xB.z); fma2(a0, xx, wlo[6]); fma2(a1, xx, whi[6]);
            xx = pack2(xB.w, xB.w); fma2(a0, xx, wlo[7]); fma2(a1, xx, whi[7]);
            ull nn = pack2(nm, nm);
            mul2(a0, nn); mul2(a1, nn);
            float f0, f1, f2, f3;
            unpack2(a0, f0, f1);
            unpack2(a1, f2, f3);
            red4(&g_tmp2[(size_t)rc.y * 128 + b * 16 + q * 4], f0, f1, f2, f3);
        }
        xA = yA; xB = yB; jc = jn; vc = vn; rc = rn;
    }
}

// ---------------------------------------------------------------------------
// Final: out = m + sqrt(softplus(raw_v)+1e-8) * eps   (float4 vectorized)
// ---------------------------------------------------------------------------
__global__ void k_final(const float* __restrict__ eps,
                        float* __restrict__ out,
                        int n) {
    int gi = blockIdx.x * blockDim.x + threadIdx.x;
    int total = n * 16;
    if (gi < total) {
        int node = gi >> 4, c4 = gi & 15;
        const float4* t2 = (const float4*)g_tmp2;
        float4 m = t2[(size_t)node * 32 + c4];
        float4 rv = t2[(size_t)node * 32 + 16 + c4];
        float4 e = ((const float4*)eps)[gi];
        float4 o;
        float sp;
        sp = (rv.x > 20.f) ? rv.x : log1pf(expf(rv.x)); o.x = m.x + sqrtf(sp + 1e-8f) * e.x;
        sp = (rv.y > 20.f) ? rv.y : log1pf(expf(rv.y)); o.y = m.y + sqrtf(sp + 1e-8f) * e.y;
        sp = (rv.z > 20.f) ? rv.z : log1pf(expf(rv.z)); o.z = m.z + sqrtf(sp + 1e-8f) * e.z;
        sp = (rv.w > 20.f) ? rv.w : log1pf(expf(rv.w)); o.w = m.w + sqrtf(sp + 1e-8f) * e.w;
        ((float4*)out)[gi] = o;
    }
}

// ---------------------------------------------------------------------------
extern "C" void kernel_launch(void* const* d_in, const int* in_sizes, int n_in,
                              void* d_out, int out_size) {
    const float* emb   = (const float*)d_in[0];
    const float* norm  = (const float*)d_in[1];
    const float* eps   = (const float*)d_in[2];
    const float* w1    = (const float*)d_in[3];
    const float* lw1   = (const float*)d_in[4];
    const float* b1    = (const float*)d_in[5];
    const float* w2    = (const float*)d_in[6];
    const float* lw2   = (const float*)d_in[7];
    const float* b2    = (const float*)d_in[8];
    const int*   h_ids = (const int*)d_in[9];
    const int*   src   = (const int*)d_in[10];
    const int*   dst   = (const int*)d_in[11];
    const int*   rel   = (const int*)d_in[12];

    int n  = in_sizes[9];
    int ne = in_sizes[10];

    int maxb = ne / CHUNK + NREL + 1;
    int sblocks = (ne + SCHUNK - 1) / SCHUNK;

    k_hist<<<96, 256>>>(rel, ne);
    k_scan<<<1, 256>>>();
    k_scatter<<<sblocks, 256>>>(rel, src, dst, norm, h_ids, ne);

    k_loop1<<<(n + 63) / 64, 256>>>(emb, h_ids, lw1, b1, n);
    k_edge1s<<<maxb, 256>>>(emb, w1);
    k_loop2<<<(n + 31) / 32, 256>>>(lw2, b2, n);
    k_edge2s<<<maxb, 256>>>(w2);
    k_final<<<(n * 16 + 255) / 256, 256>>>(eps, (float*)d_out, n);
}